// round 1
// baseline (speedup 1.0000x reference)
#include <cuda_runtime.h>
#include <math.h>

#define BCNT 16
#define SEQ  2048
#define HID  1024
#define MTOT (BCNT*SEQ)   // 32768

// ---- scratch (static device globals: allocation-free per harness rules) ----
__device__ float g_M[HID*HID];                       // Wq^T Wk      (4 MB)
__device__ float g_G[(size_t)MTOT*HID];              // x @ M        (134 MB)
__device__ float g_E[(size_t)BCNT*SEQ*SEQ];          // energy       (256 MB)
__device__ float g_U[BCNT*HID];                      // w @ x        (64 KB)

// ============================================================================
// Classic 128x128x8 SGEMM, 256 threads, 8x8 per-thread tile.
// All dims assumed multiples of 128 (M,N) and 8 (K) — true for all our shapes.
// Three layout variants share the same inner loop; smem tiles are k-major
// padded [8][132] to kill store bank conflicts on transposed fills.
// ============================================================================

#define GEMM_COMPUTE()                                                         \
    _Pragma("unroll")                                                          \
    for (int kk = 0; kk < 8; kk++) {                                           \
        float a[8], bb[8];                                                     \
        *(float4*)(a)     = *(const float4*)&As[kk][ty*8];                     \
        *(float4*)(a + 4) = *(const float4*)&As[kk][ty*8 + 4];                 \
        *(float4*)(bb)     = *(const float4*)&Bs[kk][tx*8];                    \
        *(float4*)(bb + 4) = *(const float4*)&Bs[kk][tx*8 + 4];                \
        _Pragma("unroll")                                                      \
        for (int i = 0; i < 8; i++)                                            \
            _Pragma("unroll")                                                  \
            for (int j = 0; j < 8; j++)                                        \
                acc[i][j] = fmaf(a[i], bb[j], acc[i][j]);                      \
    }

#define GEMM_EPILOGUE(Cbase, ldc)                                              \
    _Pragma("unroll")                                                          \
    for (int i = 0; i < 8; i++) {                                              \
        float4 v0, v1;                                                         \
        v0.x = acc[i][0]*scale; v0.y = acc[i][1]*scale;                        \
        v0.z = acc[i][2]*scale; v0.w = acc[i][3]*scale;                        \
        v1.x = acc[i][4]*scale; v1.y = acc[i][5]*scale;                        \
        v1.z = acc[i][6]*scale; v1.w = acc[i][7]*scale;                        \
        float* cp = (Cbase) + (size_t)(m0 + ty*8 + i) * (ldc) + n0 + tx*8;     \
        *(float4*)cp       = v0;                                               \
        *(float4*)(cp + 4) = v1;                                               \
    }

// C[M,N] = scale * A[K,M] * B[K,N]   (TN: both operands loaded direct, k-major)
__global__ __launch_bounds__(256) void gemm_tn_kernel(
    const float* __restrict__ A, const float* __restrict__ B,
    float* __restrict__ C, int Mdim, int Ndim, int Kdim, float scale)
{
    __shared__ float As[8][132];
    __shared__ float Bs[8][132];
    const int tid = threadIdx.x;
    const int m0 = blockIdx.y * 128, n0 = blockIdx.x * 128;
    const int dr = tid >> 5, dc = (tid & 31) * 4;   // direct loader: row 0..7, col4
    const int tx = tid & 15, ty = tid >> 4;
    float acc[8][8];
    #pragma unroll
    for (int i = 0; i < 8; i++)
        #pragma unroll
        for (int j = 0; j < 8; j++) acc[i][j] = 0.f;

    for (int k0 = 0; k0 < Kdim; k0 += 8) {
        float4 av = *(const float4*)(A + (size_t)(k0 + dr) * Mdim + m0 + dc);
        float4 bv = *(const float4*)(B + (size_t)(k0 + dr) * Ndim + n0 + dc);
        __syncthreads();
        *(float4*)&As[dr][dc] = av;
        *(float4*)&Bs[dr][dc] = bv;
        __syncthreads();
        GEMM_COMPUTE();
    }
    GEMM_EPILOGUE(C, Ndim);
}

// C[M,N] = scale * A[M,K] * B[K,N]   (NN: A transposed on fill, B direct)
__global__ __launch_bounds__(256) void gemm_nn_kernel(
    const float* __restrict__ A, const float* __restrict__ B,
    float* __restrict__ C, int Mdim, int Ndim, int Kdim, float scale)
{
    __shared__ float As[8][132];
    __shared__ float Bs[8][132];
    const int tid = threadIdx.x;
    const int m0 = blockIdx.y * 128, n0 = blockIdx.x * 128;
    const int lr = tid >> 1, lk = (tid & 1) * 4;    // transposed loader
    const int dr = tid >> 5, dc = (tid & 31) * 4;   // direct loader
    const int tx = tid & 15, ty = tid >> 4;
    float acc[8][8];
    #pragma unroll
    for (int i = 0; i < 8; i++)
        #pragma unroll
        for (int j = 0; j < 8; j++) acc[i][j] = 0.f;

    for (int k0 = 0; k0 < Kdim; k0 += 8) {
        float4 av = *(const float4*)(A + (size_t)(m0 + lr) * Kdim + k0 + lk);
        float4 bv = *(const float4*)(B + (size_t)(k0 + dr) * Ndim + n0 + dc);
        __syncthreads();
        As[lk + 0][lr] = av.x; As[lk + 1][lr] = av.y;
        As[lk + 2][lr] = av.z; As[lk + 3][lr] = av.w;
        *(float4*)&Bs[dr][dc] = bv;
        __syncthreads();
        GEMM_COMPUTE();
    }
    GEMM_EPILOGUE(C, Ndim);
}

// C[z][M,N] = scale * A[z][M,K] * B[z][N,K]^T   (NT batched: both transposed fill)
__global__ __launch_bounds__(256) void gemm_nt_kernel(
    const float* __restrict__ A, const float* __restrict__ B,
    float* __restrict__ C, int Mdim, int Ndim, int Kdim, float scale,
    size_t aBatch, size_t bBatch, size_t cBatch)
{
    __shared__ float As[8][132];
    __shared__ float Bs[8][132];
    const int tid = threadIdx.x;
    const int m0 = blockIdx.y * 128, n0 = blockIdx.x * 128;
    const float* Az = A + (size_t)blockIdx.z * aBatch;
    const float* Bz = B + (size_t)blockIdx.z * bBatch;
    float* Cz = C + (size_t)blockIdx.z * cBatch;
    const int lr = tid >> 1, lk = (tid & 1) * 4;
    const int tx = tid & 15, ty = tid >> 4;
    float acc[8][8];
    #pragma unroll
    for (int i = 0; i < 8; i++)
        #pragma unroll
        for (int j = 0; j < 8; j++) acc[i][j] = 0.f;

    for (int k0 = 0; k0 < Kdim; k0 += 8) {
        float4 av = *(const float4*)(Az + (size_t)(m0 + lr) * Kdim + k0 + lk);
        float4 bv = *(const float4*)(Bz + (size_t)(n0 + lr) * Kdim + k0 + lk);
        __syncthreads();
        As[lk + 0][lr] = av.x; As[lk + 1][lr] = av.y;
        As[lk + 2][lr] = av.z; As[lk + 3][lr] = av.w;
        Bs[lk + 0][lr] = bv.x; Bs[lk + 1][lr] = bv.y;
        Bs[lk + 2][lr] = bv.z; Bs[lk + 3][lr] = bv.w;
        __syncthreads();
        GEMM_COMPUTE();
    }
    GEMM_EPILOGUE(Cz, Ndim);
}

// ============================================================================
// Softmax over each E row + mean over q into w[b,k].
// Block = 256 threads (8 warps), handles 128 q-rows (warp r takes 16 rows).
// Per-warp accumulators live in 64 registers/lane (lane owns k = lane+32j).
// Combine: smem atomics (cheap, spread) then 2048 global atomics per block.
// ============================================================================
__global__ __launch_bounds__(256) void softmax_w_kernel(float* __restrict__ w)
{
    __shared__ float ws[SEQ];
    const int b = blockIdx.y;
    const int qbase = blockIdx.x * 128;
    const int tid = threadIdx.x, lane = tid & 31, warp = tid >> 5;

    for (int i = tid; i < SEQ; i += 256) ws[i] = 0.f;
    __syncthreads();

    float acc[64];
    #pragma unroll
    for (int j = 0; j < 64; j++) acc[j] = 0.f;

    const float* Eb = g_E + (size_t)b * SEQ * SEQ;
    for (int r = 0; r < 16; r++) {
        const int q = qbase + warp * 16 + r;
        const float* row = Eb + (size_t)q * SEQ;
        float m = -1e30f;
        #pragma unroll 8
        for (int j = 0; j < 64; j++) m = fmaxf(m, row[lane + 32 * j]);
        #pragma unroll
        for (int o = 16; o; o >>= 1) m = fmaxf(m, __shfl_xor_sync(~0u, m, o));
        float z = 0.f;
        #pragma unroll 8
        for (int j = 0; j < 64; j++) z += __expf(row[lane + 32 * j] - m);
        #pragma unroll
        for (int o = 16; o; o >>= 1) z += __shfl_xor_sync(~0u, z, o);
        const float inv = 1.0f / z;
        #pragma unroll 8
        for (int j = 0; j < 64; j++)
            acc[j] += __expf(row[lane + 32 * j] - m) * inv;
    }

    #pragma unroll 8
    for (int j = 0; j < 64; j++) atomicAdd(&ws[lane + 32 * j], acc[j]);
    __syncthreads();
    const float invS = 1.0f / (float)SEQ;
    for (int k = tid; k < SEQ; k += 256)
        atomicAdd(&w[b * SEQ + k], ws[k] * invS);
}

// u[b,h] = sum_s w[b,s] * x[b,s,h]   (grid.z splits s into 8 chunks of 256)
__global__ __launch_bounds__(256) void ctx_u_kernel(
    const float* __restrict__ x, const float* __restrict__ w)
{
    const int b = blockIdx.y;
    const int h = blockIdx.x * 256 + threadIdx.x;
    const int s0 = blockIdx.z * 256;
    const float* xb = x + ((size_t)b * SEQ + s0) * HID + h;
    const float* wb = w + b * SEQ + s0;
    float acc = 0.f;
    #pragma unroll 4
    for (int s = 0; s < 256; s++)
        acc = fmaf(wb[s], xb[(size_t)s * HID], acc);
    atomicAdd(&g_U[b * HID + h], acc);
}

// context[b,o] = sum_h u[b,h] * Wv[o,h]  — one warp per output element
__global__ __launch_bounds__(256) void ctx_out_kernel(
    const float* __restrict__ Wv, float* __restrict__ ctx)
{
    const int gid = blockIdx.x * 8 + (threadIdx.x >> 5);
    const int lane = threadIdx.x & 31;
    const int b = gid >> 10;          // /1024
    const int o = gid & 1023;
    const float* ur = g_U + b * HID;
    const float* wr = Wv + (size_t)o * HID;
    float a = 0.f;
    #pragma unroll 8
    for (int h = lane; h < HID; h += 32) a = fmaf(ur[h], wr[h], a);
    #pragma unroll
    for (int off = 16; off; off >>= 1) a += __shfl_xor_sync(~0u, a, off);
    if (lane == 0) ctx[b * HID + o] = a;
}

__global__ void init_kernel(float* __restrict__ w)
{
    const int i = blockIdx.x * 256 + threadIdx.x;
    if (i < BCNT * SEQ) w[i] = 0.f;
    if (i < BCNT * HID) g_U[i] = 0.f;
}

// ============================================================================
extern "C" void kernel_launch(void* const* d_in, const int* in_sizes, int n_in,
                              void* d_out, int out_size)
{
    const float* x  = (const float*)d_in[0];   // (16,2048,1024)
    const float* Wq = (const float*)d_in[1];   // (1024,1024) (out,in)
    const float* Wk = (const float*)d_in[2];
    const float* Wv = (const float*)d_in[3];
    float* out = (float*)d_out;
    float* ctx = out;                  // context      (16,1024)
    float* w   = out + BCNT * HID;     // attn_weights (16,2048)

    float *pM, *pG, *pE;
    cudaGetSymbolAddress((void**)&pM, g_M);
    cudaGetSymbolAddress((void**)&pG, g_G);
    cudaGetSymbolAddress((void**)&pE, g_E);

    // zero w accumulator and u accumulator
    init_kernel<<<128, 256>>>(w);

    // M = Wq^T @ Wk            (1024x1024, K=1024 over the 'out' dim)
    gemm_tn_kernel<<<dim3(8, 8), 256>>>(Wq, Wk, pM, HID, HID, HID, 1.0f);

    // G = x @ M                (32768x1024, K=1024)
    gemm_nn_kernel<<<dim3(8, 256), 256>>>(x, pM, pG, MTOT, HID, HID, 1.0f);

    // E[b] = G[b] @ x[b]^T / sqrt(H)   (16 batches of 2048x2048, K=1024)
    gemm_nt_kernel<<<dim3(16, 16, BCNT), 256>>>(
        pG, x, pE, SEQ, SEQ, HID, 1.0f / 32.0f,
        (size_t)SEQ * HID, (size_t)SEQ * HID, (size_t)SEQ * SEQ);

    // softmax rows of E, mean over q -> w[b,k]
    softmax_w_kernel<<<dim3(16, BCNT), 256>>>(w);

    // u = w @ x ; context = u @ Wv^T
    ctx_u_kernel<<<dim3(4, BCNT, 8), 256>>>(x, w);
    ctx_out_kernel<<<BCNT * HID / 8, 256>>>(Wv, ctx);
}

// round 2
// speedup vs baseline: 2.2033x; 2.2033x over previous
#include <cuda_runtime.h>
#include <math.h>
#include <stdint.h>

#define BCNT 16
#define SEQ  2048
#define HID  1024
#define MTOT (BCNT*SEQ)   // 32768

// ---- scratch (static device globals: allocation-free per harness rules) ----
__device__ float g_Mt[HID*HID];                      // Wk^T Wq = (Wq^T Wk)^T  (4 MB)
__device__ float g_G[(size_t)MTOT*HID];              // x @ M                  (134 MB)
__device__ float g_E[(size_t)BCNT*SEQ*SEQ];          // energy                 (256 MB)
__device__ float g_U[BCNT*HID];                      // w @ x                  (64 KB)

// ============================================================================
// fp32 TN GEMM (small, kept full precision): C[M,N] = A[K,M]^T B[K,N]
// ============================================================================
__global__ __launch_bounds__(256) void gemm_tn_kernel(
    const float* __restrict__ A, const float* __restrict__ B,
    float* __restrict__ C, int Mdim, int Ndim, int Kdim, float scale)
{
    __shared__ float As[8][132];
    __shared__ float Bs[8][132];
    const int tid = threadIdx.x;
    const int m0 = blockIdx.y * 128, n0 = blockIdx.x * 128;
    const int dr = tid >> 5, dc = (tid & 31) * 4;
    const int tx = tid & 15, ty = tid >> 4;
    float acc[8][8];
    #pragma unroll
    for (int i = 0; i < 8; i++)
        #pragma unroll
        for (int j = 0; j < 8; j++) acc[i][j] = 0.f;

    for (int k0 = 0; k0 < Kdim; k0 += 8) {
        float4 av = *(const float4*)(A + (size_t)(k0 + dr) * Mdim + m0 + dc);
        float4 bv = *(const float4*)(B + (size_t)(k0 + dr) * Ndim + n0 + dc);
        __syncthreads();
        *(float4*)&As[dr][dc] = av;
        *(float4*)&Bs[dr][dc] = bv;
        __syncthreads();
        #pragma unroll
        for (int kk = 0; kk < 8; kk++) {
            float a[8], bb[8];
            *(float4*)(a)     = *(const float4*)&As[kk][ty*8];
            *(float4*)(a + 4) = *(const float4*)&As[kk][ty*8 + 4];
            *(float4*)(bb)     = *(const float4*)&Bs[kk][tx*8];
            *(float4*)(bb + 4) = *(const float4*)&Bs[kk][tx*8 + 4];
            #pragma unroll
            for (int i = 0; i < 8; i++)
                #pragma unroll
                for (int j = 0; j < 8; j++)
                    acc[i][j] = fmaf(a[i], bb[j], acc[i][j]);
        }
    }
    #pragma unroll
    for (int i = 0; i < 8; i++) {
        float* cp = C + (size_t)(m0 + ty*8 + i) * Ndim + n0 + tx*8;
        #pragma unroll
        for (int j = 0; j < 8; j++) cp[j] = acc[i][j] * scale;
    }
}

// ============================================================================
// tf32 tensor-core NT GEMM (batched):
//   C[z][M,N] = scale * A[z][M,K] @ B[z][N,K]^T
// Block tile 128x128, BK=16, 8 warps (2m x 4n), warp tile 64x32,
// mma.sync.m16n8k8.tf32. Smem row stride 20 words => conflict-free fragment
// loads (20*r mod 32 cycles 0,20,8,28,16,4,24,12 — all distinct).
// ============================================================================
__device__ __forceinline__ uint32_t f2tf(float f) {
    uint32_t u;
    asm("cvt.rna.tf32.f32 %0, %1;" : "=r"(u) : "f"(f));
    return u;
}

__device__ __forceinline__ void mma_tf32(float c[4], uint32_t a0, uint32_t a1,
                                         uint32_t a2, uint32_t a3,
                                         uint32_t b0, uint32_t b1)
{
    asm volatile(
        "mma.sync.aligned.m16n8k8.row.col.f32.tf32.tf32.f32 "
        "{%0,%1,%2,%3}, {%4,%5,%6,%7}, {%8,%9}, {%0,%1,%2,%3};"
        : "+f"(c[0]), "+f"(c[1]), "+f"(c[2]), "+f"(c[3])
        : "r"(a0), "r"(a1), "r"(a2), "r"(a3), "r"(b0), "r"(b1));
}

__global__ __launch_bounds__(256) void gemm_nt_tf32(
    const float* __restrict__ A, const float* __restrict__ B,
    float* __restrict__ C, int Ndim, int Kdim, float scale,
    size_t aBatch, size_t bBatch, size_t cBatch)
{
    __shared__ uint32_t As[128][20];
    __shared__ uint32_t Bs[128][20];

    const int tid  = threadIdx.x;
    const int lane = tid & 31;
    const int warp = tid >> 5;
    const int warp_m = warp & 1;   // 2 warps along m
    const int warp_n = warp >> 1;  // 4 warps along n
    const int m0 = blockIdx.y * 128, n0 = blockIdx.x * 128;

    const float* Az = A + (size_t)blockIdx.z * aBatch;
    const float* Bz = B + (size_t)blockIdx.z * bBatch;
    float*       Cz = C + (size_t)blockIdx.z * cBatch;

    // loader mapping: quad q -> row = q>>2, kq = q&3 ; thread handles q=tid, q=tid+256
    const int lrow = tid >> 2;
    const int lkq  = (tid & 3) * 4;
    const float* aPtr = Az + (size_t)(m0 + lrow) * Kdim + lkq;
    const float* bPtr = Bz + (size_t)(n0 + lrow) * Kdim + lkq;

    float acc[4][4][4];
    #pragma unroll
    for (int i = 0; i < 4; i++)
        #pragma unroll
        for (int j = 0; j < 4; j++)
            #pragma unroll
            for (int k = 0; k < 4; k++) acc[i][j][k] = 0.f;

    // prologue: stage k0 = 0
    float4 ra0 = *(const float4*)(aPtr);
    float4 ra1 = *(const float4*)(aPtr + (size_t)64 * Kdim);
    float4 rb0 = *(const float4*)(bPtr);
    float4 rb1 = *(const float4*)(bPtr + (size_t)64 * Kdim);
    {
        uint32_t* da0 = &As[lrow][lkq];
        uint32_t* da1 = &As[lrow + 64][lkq];
        uint32_t* db0 = &Bs[lrow][lkq];
        uint32_t* db1 = &Bs[lrow + 64][lkq];
        da0[0]=f2tf(ra0.x); da0[1]=f2tf(ra0.y); da0[2]=f2tf(ra0.z); da0[3]=f2tf(ra0.w);
        da1[0]=f2tf(ra1.x); da1[1]=f2tf(ra1.y); da1[2]=f2tf(ra1.z); da1[3]=f2tf(ra1.w);
        db0[0]=f2tf(rb0.x); db0[1]=f2tf(rb0.y); db0[2]=f2tf(rb0.z); db0[3]=f2tf(rb0.w);
        db1[0]=f2tf(rb1.x); db1[1]=f2tf(rb1.y); db1[2]=f2tf(rb1.z); db1[3]=f2tf(rb1.w);
    }
    __syncthreads();

    for (int k0 = 0; k0 < Kdim; k0 += 16) {
        const bool has_next = (k0 + 16) < Kdim;
        if (has_next) {
            const float* ap = aPtr + k0 + 16;
            const float* bp = bPtr + k0 + 16;
            ra0 = *(const float4*)(ap);
            ra1 = *(const float4*)(ap + (size_t)64 * Kdim);
            rb0 = *(const float4*)(bp);
            rb1 = *(const float4*)(bp + (size_t)64 * Kdim);
        }

        #pragma unroll
        for (int kk = 0; kk < 16; kk += 8) {
            uint32_t bfr[4][2];
            #pragma unroll
            for (int wn = 0; wn < 4; wn++) {
                const int br = warp_n * 32 + wn * 8 + (lane >> 2);
                bfr[wn][0] = Bs[br][kk + (lane & 3)];
                bfr[wn][1] = Bs[br][kk + 4 + (lane & 3)];
            }
            #pragma unroll
            for (int wm = 0; wm < 4; wm++) {
                const int ar = warp_m * 64 + wm * 16 + (lane >> 2);
                uint32_t a0 = As[ar][kk + (lane & 3)];
                uint32_t a1 = As[ar + 8][kk + (lane & 3)];
                uint32_t a2 = As[ar][kk + 4 + (lane & 3)];
                uint32_t a3 = As[ar + 8][kk + 4 + (lane & 3)];
                #pragma unroll
                for (int wn = 0; wn < 4; wn++)
                    mma_tf32(acc[wm][wn], a0, a1, a2, a3, bfr[wn][0], bfr[wn][1]);
            }
        }

        __syncthreads();
        if (has_next) {
            uint32_t* da0 = &As[lrow][lkq];
            uint32_t* da1 = &As[lrow + 64][lkq];
            uint32_t* db0 = &Bs[lrow][lkq];
            uint32_t* db1 = &Bs[lrow + 64][lkq];
            da0[0]=f2tf(ra0.x); da0[1]=f2tf(ra0.y); da0[2]=f2tf(ra0.z); da0[3]=f2tf(ra0.w);
            da1[0]=f2tf(ra1.x); da1[1]=f2tf(ra1.y); da1[2]=f2tf(ra1.z); da1[3]=f2tf(ra1.w);
            db0[0]=f2tf(rb0.x); db0[1]=f2tf(rb0.y); db0[2]=f2tf(rb0.z); db0[3]=f2tf(rb0.w);
            db1[0]=f2tf(rb1.x); db1[1]=f2tf(rb1.y); db1[2]=f2tf(rb1.z); db1[3]=f2tf(rb1.w);
            __syncthreads();
        }
    }

    // epilogue
    #pragma unroll
    for (int wm = 0; wm < 4; wm++) {
        const int r = m0 + warp_m * 64 + wm * 16 + (lane >> 2);
        #pragma unroll
        for (int wn = 0; wn < 4; wn++) {
            const int c = n0 + warp_n * 32 + wn * 8 + 2 * (lane & 3);
            float2 v0, v1;
            v0.x = acc[wm][wn][0] * scale; v0.y = acc[wm][wn][1] * scale;
            v1.x = acc[wm][wn][2] * scale; v1.y = acc[wm][wn][3] * scale;
            *(float2*)&Cz[(size_t)r * Ndim + c]       = v0;
            *(float2*)&Cz[(size_t)(r + 8) * Ndim + c] = v1;
        }
    }
}

// ============================================================================
// Softmax over each E row + mean over q into w[b,k]. (unchanged from R1)
// ============================================================================
__global__ __launch_bounds__(256) void softmax_w_kernel(float* __restrict__ w)
{
    __shared__ float ws[SEQ];
    const int b = blockIdx.y;
    const int qbase = blockIdx.x * 128;
    const int tid = threadIdx.x, lane = tid & 31, warp = tid >> 5;

    for (int i = tid; i < SEQ; i += 256) ws[i] = 0.f;
    __syncthreads();

    float acc[64];
    #pragma unroll
    for (int j = 0; j < 64; j++) acc[j] = 0.f;

    const float* Eb = g_E + (size_t)b * SEQ * SEQ;
    for (int r = 0; r < 16; r++) {
        const int q = qbase + warp * 16 + r;
        const float* row = Eb + (size_t)q * SEQ;
        float m = -1e30f;
        #pragma unroll 8
        for (int j = 0; j < 64; j++) m = fmaxf(m, row[lane + 32 * j]);
        #pragma unroll
        for (int o = 16; o; o >>= 1) m = fmaxf(m, __shfl_xor_sync(~0u, m, o));
        float z = 0.f;
        #pragma unroll 8
        for (int j = 0; j < 64; j++) z += __expf(row[lane + 32 * j] - m);
        #pragma unroll
        for (int o = 16; o; o >>= 1) z += __shfl_xor_sync(~0u, z, o);
        const float inv = 1.0f / z;
        #pragma unroll 8
        for (int j = 0; j < 64; j++)
            acc[j] += __expf(row[lane + 32 * j] - m) * inv;
    }

    #pragma unroll 8
    for (int j = 0; j < 64; j++) atomicAdd(&ws[lane + 32 * j], acc[j]);
    __syncthreads();
    const float invS = 1.0f / (float)SEQ;
    for (int k = tid; k < SEQ; k += 256)
        atomicAdd(&w[b * SEQ + k], ws[k] * invS);
}

// u[b,h] = sum_s w[b,s] * x[b,s,h]
__global__ __launch_bounds__(256) void ctx_u_kernel(
    const float* __restrict__ x, const float* __restrict__ w)
{
    const int b = blockIdx.y;
    const int h = blockIdx.x * 256 + threadIdx.x;
    const int s0 = blockIdx.z * 256;
    const float* xb = x + ((size_t)b * SEQ + s0) * HID + h;
    const float* wb = w + b * SEQ + s0;
    float acc = 0.f;
    #pragma unroll 4
    for (int s = 0; s < 256; s++)
        acc = fmaf(wb[s], xb[(size_t)s * HID], acc);
    atomicAdd(&g_U[b * HID + h], acc);
}

// context[b,o] = sum_h u[b,h] * Wv[o,h]
__global__ __launch_bounds__(256) void ctx_out_kernel(
    const float* __restrict__ Wv, float* __restrict__ ctx)
{
    const int gid = blockIdx.x * 8 + (threadIdx.x >> 5);
    const int lane = threadIdx.x & 31;
    const int b = gid >> 10;
    const int o = gid & 1023;
    const float* ur = g_U + b * HID;
    const float* wr = Wv + (size_t)o * HID;
    float a = 0.f;
    #pragma unroll 8
    for (int h = lane; h < HID; h += 32) a = fmaf(ur[h], wr[h], a);
    #pragma unroll
    for (int off = 16; off; off >>= 1) a += __shfl_xor_sync(~0u, a, off);
    if (lane == 0) ctx[b * HID + o] = a;
}

__global__ void init_kernel(float* __restrict__ w)
{
    const int i = blockIdx.x * 256 + threadIdx.x;
    if (i < BCNT * SEQ) w[i] = 0.f;
    if (i < BCNT * HID) g_U[i] = 0.f;
}

// ============================================================================
extern "C" void kernel_launch(void* const* d_in, const int* in_sizes, int n_in,
                              void* d_out, int out_size)
{
    const float* x  = (const float*)d_in[0];   // (16,2048,1024)
    const float* Wq = (const float*)d_in[1];   // (1024,1024) (out,in)
    const float* Wk = (const float*)d_in[2];
    const float* Wv = (const float*)d_in[3];
    float* out = (float*)d_out;
    float* ctx = out;                  // context      (16,1024)
    float* w   = out + BCNT * HID;     // attn_weights (16,2048)

    float *pMt, *pG, *pE;
    cudaGetSymbolAddress((void**)&pMt, g_Mt);
    cudaGetSymbolAddress((void**)&pG, g_G);
    cudaGetSymbolAddress((void**)&pE, g_E);

    init_kernel<<<128, 256>>>(w);

    // Mt = Wk^T @ Wq  (= M^T where M = Wq^T Wk), fp32-exact
    gemm_tn_kernel<<<dim3(8, 8), 256>>>(Wk, Wq, pMt, HID, HID, HID, 1.0f);

    // G = x @ Mt^T   (32768x1024, K=1024) — tf32 NT
    gemm_nt_tf32<<<dim3(8, 256, 1), 256>>>(
        x, pMt, pG, HID, HID, 1.0f, 0, 0, 0);

    // E[b] = G[b] @ x[b]^T / 32   (16 x 2048x2048, K=1024) — tf32 NT
    gemm_nt_tf32<<<dim3(16, 16, BCNT), 256>>>(
        pG, x, pE, SEQ, HID, 1.0f / 32.0f,
        (size_t)SEQ * HID, (size_t)SEQ * HID, (size_t)SEQ * SEQ);

    // softmax rows of E, mean over q -> w[b,k]
    softmax_w_kernel<<<dim3(16, BCNT), 256>>>(w);

    // u = w @ x ; context = u @ Wv^T
    ctx_u_kernel<<<dim3(4, BCNT, 8), 256>>>(x, w);
    ctx_out_kernel<<<BCNT * HID / 8, 256>>>(Wv, ctx);
}

// round 3
// speedup vs baseline: 2.2094x; 1.0028x over previous
#include <cuda_runtime.h>
#include <math.h>
#include <stdint.h>

#define BCNT 16
#define SEQ  2048
#define HID  1024
#define MTOT (BCNT*SEQ)   // 32768

// ---- scratch (static device globals: allocation-free per harness rules) ----
__device__ float g_Mt[HID*HID];                      // Wk^T Wq = (Wq^T Wk)^T  (4 MB)
__device__ float g_G[(size_t)MTOT*HID];              // x @ M                  (134 MB)
__device__ float g_E[(size_t)BCNT*SEQ*SEQ];          // energy                 (256 MB)
__device__ float g_U[BCNT*HID];                      // w @ x                  (64 KB)

// ============================================================================
// fp32 TN GEMM (small, kept full precision): C[M,N] = A[K,M]^T B[K,N]
// ============================================================================
__global__ __launch_bounds__(256) void gemm_tn_kernel(
    const float* __restrict__ A, const float* __restrict__ B,
    float* __restrict__ C, int Mdim, int Ndim, int Kdim, float scale)
{
    __shared__ float As[8][132];
    __shared__ float Bs[8][132];
    const int tid = threadIdx.x;
    const int m0 = blockIdx.y * 128, n0 = blockIdx.x * 128;
    const int dr = tid >> 5, dc = (tid & 31) * 4;
    const int tx = tid & 15, ty = tid >> 4;
    float acc[8][8];
    #pragma unroll
    for (int i = 0; i < 8; i++)
        #pragma unroll
        for (int j = 0; j < 8; j++) acc[i][j] = 0.f;

    for (int k0 = 0; k0 < Kdim; k0 += 8) {
        float4 av = *(const float4*)(A + (size_t)(k0 + dr) * Mdim + m0 + dc);
        float4 bv = *(const float4*)(B + (size_t)(k0 + dr) * Ndim + n0 + dc);
        __syncthreads();
        *(float4*)&As[dr][dc] = av;
        *(float4*)&Bs[dr][dc] = bv;
        __syncthreads();
        #pragma unroll
        for (int kk = 0; kk < 8; kk++) {
            float a[8], bb[8];
            *(float4*)(a)     = *(const float4*)&As[kk][ty*8];
            *(float4*)(a + 4) = *(const float4*)&As[kk][ty*8 + 4];
            *(float4*)(bb)     = *(const float4*)&Bs[kk][tx*8];
            *(float4*)(bb + 4) = *(const float4*)&Bs[kk][tx*8 + 4];
            #pragma unroll
            for (int i = 0; i < 8; i++)
                #pragma unroll
                for (int j = 0; j < 8; j++)
                    acc[i][j] = fmaf(a[i], bb[j], acc[i][j]);
        }
    }
    #pragma unroll
    for (int i = 0; i < 8; i++) {
        float* cp = C + (size_t)(m0 + ty*8 + i) * Ndim + n0 + tx*8;
        #pragma unroll
        for (int j = 0; j < 8; j++) cp[j] = acc[i][j] * scale;
    }
}

// ============================================================================
// tf32 tensor-core NT GEMM (batched):
//   C[z][M,N] = scale * A[z][M,K] @ B[z][N,K]^T
// Block tile 128x128, BK=16, 8 warps (2m x 4n), warp tile 64x32,
// mma.sync.m16n8k8.tf32. Smem row stride 20 words => conflict-free fragment
// loads (20*r mod 32 cycles 0,20,8,28,16,4,24,12 — all distinct).
// ============================================================================
__device__ __forceinline__ uint32_t f2tf(float f) {
    uint32_t u;
    asm("cvt.rna.tf32.f32 %0, %1;" : "=r"(u) : "f"(f));
    return u;
}

__device__ __forceinline__ void mma_tf32(float c[4], uint32_t a0, uint32_t a1,
                                         uint32_t a2, uint32_t a3,
                                         uint32_t b0, uint32_t b1)
{
    asm volatile(
        "mma.sync.aligned.m16n8k8.row.col.f32.tf32.tf32.f32 "
        "{%0,%1,%2,%3}, {%4,%5,%6,%7}, {%8,%9}, {%0,%1,%2,%3};"
        : "+f"(c[0]), "+f"(c[1]), "+f"(c[2]), "+f"(c[3])
        : "r"(a0), "r"(a1), "r"(a2), "r"(a3), "r"(b0), "r"(b1));
}

__global__ __launch_bounds__(256) void gemm_nt_tf32(
    const float* __restrict__ A, const float* __restrict__ B,
    float* __restrict__ C, int Ndim, int Kdim, float scale,
    size_t aBatch, size_t bBatch, size_t cBatch)
{
    __shared__ uint32_t As[128][20];
    __shared__ uint32_t Bs[128][20];

    const int tid  = threadIdx.x;
    const int lane = tid & 31;
    const int warp = tid >> 5;
    const int warp_m = warp & 1;   // 2 warps along m
    const int warp_n = warp >> 1;  // 4 warps along n
    const int m0 = blockIdx.y * 128, n0 = blockIdx.x * 128;

    const float* Az = A + (size_t)blockIdx.z * aBatch;
    const float* Bz = B + (size_t)blockIdx.z * bBatch;
    float*       Cz = C + (size_t)blockIdx.z * cBatch;

    // loader mapping: quad q -> row = q>>2, kq = q&3 ; thread handles q=tid, q=tid+256
    const int lrow = tid >> 2;
    const int lkq  = (tid & 3) * 4;
    const float* aPtr = Az + (size_t)(m0 + lrow) * Kdim + lkq;
    const float* bPtr = Bz + (size_t)(n0 + lrow) * Kdim + lkq;

    float acc[4][4][4];
    #pragma unroll
    for (int i = 0; i < 4; i++)
        #pragma unroll
        for (int j = 0; j < 4; j++)
            #pragma unroll
            for (int k = 0; k < 4; k++) acc[i][j][k] = 0.f;

    // prologue: stage k0 = 0
    float4 ra0 = *(const float4*)(aPtr);
    float4 ra1 = *(const float4*)(aPtr + (size_t)64 * Kdim);
    float4 rb0 = *(const float4*)(bPtr);
    float4 rb1 = *(const float4*)(bPtr + (size_t)64 * Kdim);
    {
        uint32_t* da0 = &As[lrow][lkq];
        uint32_t* da1 = &As[lrow + 64][lkq];
        uint32_t* db0 = &Bs[lrow][lkq];
        uint32_t* db1 = &Bs[lrow + 64][lkq];
        da0[0]=f2tf(ra0.x); da0[1]=f2tf(ra0.y); da0[2]=f2tf(ra0.z); da0[3]=f2tf(ra0.w);
        da1[0]=f2tf(ra1.x); da1[1]=f2tf(ra1.y); da1[2]=f2tf(ra1.z); da1[3]=f2tf(ra1.w);
        db0[0]=f2tf(rb0.x); db0[1]=f2tf(rb0.y); db0[2]=f2tf(rb0.z); db0[3]=f2tf(rb0.w);
        db1[0]=f2tf(rb1.x); db1[1]=f2tf(rb1.y); db1[2]=f2tf(rb1.z); db1[3]=f2tf(rb1.w);
    }
    __syncthreads();

    for (int k0 = 0; k0 < Kdim; k0 += 16) {
        const bool has_next = (k0 + 16) < Kdim;
        if (has_next) {
            const float* ap = aPtr + k0 + 16;
            const float* bp = bPtr + k0 + 16;
            ra0 = *(const float4*)(ap);
            ra1 = *(const float4*)(ap + (size_t)64 * Kdim);
            rb0 = *(const float4*)(bp);
            rb1 = *(const float4*)(bp + (size_t)64 * Kdim);
        }

        #pragma unroll
        for (int kk = 0; kk < 16; kk += 8) {
            uint32_t bfr[4][2];
            #pragma unroll
            for (int wn = 0; wn < 4; wn++) {
                const int br = warp_n * 32 + wn * 8 + (lane >> 2);
                bfr[wn][0] = Bs[br][kk + (lane & 3)];
                bfr[wn][1] = Bs[br][kk + 4 + (lane & 3)];
            }
            #pragma unroll
            for (int wm = 0; wm < 4; wm++) {
                const int ar = warp_m * 64 + wm * 16 + (lane >> 2);
                uint32_t a0 = As[ar][kk + (lane & 3)];
                uint32_t a1 = As[ar + 8][kk + (lane & 3)];
                uint32_t a2 = As[ar][kk + 4 + (lane & 3)];
                uint32_t a3 = As[ar + 8][kk + 4 + (lane & 3)];
                #pragma unroll
                for (int wn = 0; wn < 4; wn++)
                    mma_tf32(acc[wm][wn], a0, a1, a2, a3, bfr[wn][0], bfr[wn][1]);
            }
        }

        __syncthreads();
        if (has_next) {
            uint32_t* da0 = &As[lrow][lkq];
            uint32_t* da1 = &As[lrow + 64][lkq];
            uint32_t* db0 = &Bs[lrow][lkq];
            uint32_t* db1 = &Bs[lrow + 64][lkq];
            da0[0]=f2tf(ra0.x); da0[1]=f2tf(ra0.y); da0[2]=f2tf(ra0.z); da0[3]=f2tf(ra0.w);
            da1[0]=f2tf(ra1.x); da1[1]=f2tf(ra1.y); da1[2]=f2tf(ra1.z); da1[3]=f2tf(ra1.w);
            db0[0]=f2tf(rb0.x); db0[1]=f2tf(rb0.y); db0[2]=f2tf(rb0.z); db0[3]=f2tf(rb0.w);
            db1[0]=f2tf(rb1.x); db1[1]=f2tf(rb1.y); db1[2]=f2tf(rb1.z); db1[3]=f2tf(rb1.w);
            __syncthreads();
        }
    }

    // epilogue
    #pragma unroll
    for (int wm = 0; wm < 4; wm++) {
        const int r = m0 + warp_m * 64 + wm * 16 + (lane >> 2);
        #pragma unroll
        for (int wn = 0; wn < 4; wn++) {
            const int c = n0 + warp_n * 32 + wn * 8 + 2 * (lane & 3);
            float2 v0, v1;
            v0.x = acc[wm][wn][0] * scale; v0.y = acc[wm][wn][1] * scale;
            v1.x = acc[wm][wn][2] * scale; v1.y = acc[wm][wn][3] * scale;
            *(float2*)&Cz[(size_t)r * Ndim + c]       = v0;
            *(float2*)&Cz[(size_t)(r + 8) * Ndim + c] = v1;
        }
    }
}

// ============================================================================
// Softmax over each E row + mean over q into w[b,k]. (unchanged from R1)
// ============================================================================
__global__ __launch_bounds__(256) void softmax_w_kernel(float* __restrict__ w)
{
    __shared__ float ws[SEQ];
    const int b = blockIdx.y;
    const int qbase = blockIdx.x * 128;
    const int tid = threadIdx.x, lane = tid & 31, warp = tid >> 5;

    for (int i = tid; i < SEQ; i += 256) ws[i] = 0.f;
    __syncthreads();

    float acc[64];
    #pragma unroll
    for (int j = 0; j < 64; j++) acc[j] = 0.f;

    const float* Eb = g_E + (size_t)b * SEQ * SEQ;
    for (int r = 0; r < 16; r++) {
        const int q = qbase + warp * 16 + r;
        const float* row = Eb + (size_t)q * SEQ;
        float m = -1e30f;
        #pragma unroll 8
        for (int j = 0; j < 64; j++) m = fmaxf(m, row[lane + 32 * j]);
        #pragma unroll
        for (int o = 16; o; o >>= 1) m = fmaxf(m, __shfl_xor_sync(~0u, m, o));
        float z = 0.f;
        #pragma unroll 8
        for (int j = 0; j < 64; j++) z += __expf(row[lane + 32 * j] - m);
        #pragma unroll
        for (int o = 16; o; o >>= 1) z += __shfl_xor_sync(~0u, z, o);
        const float inv = 1.0f / z;
        #pragma unroll 8
        for (int j = 0; j < 64; j++)
            acc[j] += __expf(row[lane + 32 * j] - m) * inv;
    }

    #pragma unroll 8
    for (int j = 0; j < 64; j++) atomicAdd(&ws[lane + 32 * j], acc[j]);
    __syncthreads();
    const float invS = 1.0f / (float)SEQ;
    for (int k = tid; k < SEQ; k += 256)
        atomicAdd(&w[b * SEQ + k], ws[k] * invS);
}

// u[b,h] = sum_s w[b,s] * x[b,s,h]
__global__ __launch_bounds__(256) void ctx_u_kernel(
    const float* __restrict__ x, const float* __restrict__ w)
{
    const int b = blockIdx.y;
    const int h = blockIdx.x * 256 + threadIdx.x;
    const int s0 = blockIdx.z * 256;
    const float* xb = x + ((size_t)b * SEQ + s0) * HID + h;
    const float* wb = w + b * SEQ + s0;
    float acc = 0.f;
    #pragma unroll 4
    for (int s = 0; s < 256; s++)
        acc = fmaf(wb[s], xb[(size_t)s * HID], acc);
    atomicAdd(&g_U[b * HID + h], acc);
}

// context[b,o] = sum_h u[b,h] * Wv[o,h]
__global__ __launch_bounds__(256) void ctx_out_kernel(
    const float* __restrict__ Wv, float* __restrict__ ctx)
{
    const int gid = blockIdx.x * 8 + (threadIdx.x >> 5);
    const int lane = threadIdx.x & 31;
    const int b = gid >> 10;
    const int o = gid & 1023;
    const float* ur = g_U + b * HID;
    const float* wr = Wv + (size_t)o * HID;
    float a = 0.f;
    #pragma unroll 8
    for (int h = lane; h < HID; h += 32) a = fmaf(ur[h], wr[h], a);
    #pragma unroll
    for (int off = 16; off; off >>= 1) a += __shfl_xor_sync(~0u, a, off);
    if (lane == 0) ctx[b * HID + o] = a;
}

__global__ void init_kernel(float* __restrict__ w)
{
    const int i = blockIdx.x * 256 + threadIdx.x;
    if (i < BCNT * SEQ) w[i] = 0.f;
    if (i < BCNT * HID) g_U[i] = 0.f;
}

// ============================================================================
extern "C" void kernel_launch(void* const* d_in, const int* in_sizes, int n_in,
                              void* d_out, int out_size)
{
    const float* x  = (const float*)d_in[0];   // (16,2048,1024)
    const float* Wq = (const float*)d_in[1];   // (1024,1024) (out,in)
    const float* Wk = (const float*)d_in[2];
    const float* Wv = (const float*)d_in[3];
    float* out = (float*)d_out;
    float* ctx = out;                  // context      (16,1024)
    float* w   = out + BCNT * HID;     // attn_weights (16,2048)

    float *pMt, *pG, *pE;
    cudaGetSymbolAddress((void**)&pMt, g_Mt);
    cudaGetSymbolAddress((void**)&pG, g_G);
    cudaGetSymbolAddress((void**)&pE, g_E);

    init_kernel<<<128, 256>>>(w);

    // Mt = Wk^T @ Wq  (= M^T where M = Wq^T Wk), fp32-exact
    gemm_tn_kernel<<<dim3(8, 8), 256>>>(Wk, Wq, pMt, HID, HID, HID, 1.0f);

    // G = x @ Mt^T   (32768x1024, K=1024) — tf32 NT
    gemm_nt_tf32<<<dim3(8, 256, 1), 256>>>(
        x, pMt, pG, HID, HID, 1.0f, 0, 0, 0);

    // E[b] = G[b] @ x[b]^T / 32   (16 x 2048x2048, K=1024) — tf32 NT
    gemm_nt_tf32<<<dim3(16, 16, BCNT), 256>>>(
        pG, x, pE, SEQ, HID, 1.0f / 32.0f,
        (size_t)SEQ * HID, (size_t)SEQ * HID, (size_t)SEQ * SEQ);

    // softmax rows of E, mean over q -> w[b,k]
    softmax_w_kernel<<<dim3(16, BCNT), 256>>>(w);

    // u = w @ x ; context = u @ Wv^T
    ctx_u_kernel<<<dim3(4, BCNT, 8), 256>>>(x, w);
    ctx_out_kernel<<<BCNT * HID / 8, 256>>>(Wv, ctx);
}

// round 4
// speedup vs baseline: 4.1734x; 1.8889x over previous
#include <cuda_runtime.h>
#include <cuda_fp16.h>
#include <math.h>
#include <stdint.h>

#define BCNT 16
#define SEQ  2048
#define HID  1024
#define MTOT (BCNT*SEQ)   // 32768

// ---- scratch (static device globals: allocation-free per harness rules) ----
__device__ __half g_xh[(size_t)MTOT*HID];            // x in fp16             (64 MB)
__device__ __half g_Mth[HID*HID];                    // (Wk^T Wq) in fp16     (2 MB)
__device__ __half g_Gh[(size_t)MTOT*HID];            // x @ M in fp16         (64 MB)
__device__ float  g_E[(size_t)BCNT*SEQ*SEQ];         // energy                (256 MB)
__device__ float  g_U[BCNT*HID];                     // w @ x                 (64 KB)

// ============================================================================
// x (fp32) -> fp16
// ============================================================================
__global__ __launch_bounds__(256) void convert_x_kernel(
    const float4* __restrict__ in, uint2* __restrict__ outp)
{
    const int i = blockIdx.x * 256 + threadIdx.x;
    float4 v = in[i];
    __half2 h0 = __floats2half2_rn(v.x, v.y);
    __half2 h1 = __floats2half2_rn(v.z, v.w);
    uint2 u;
    u.x = *(uint32_t*)&h0;
    u.y = *(uint32_t*)&h1;
    outp[i] = u;
}

// ============================================================================
// fp32 TN GEMM (small): C[M,N] = A[K,M]^T B[K,N], output fp16
// ============================================================================
__global__ __launch_bounds__(256) void gemm_tn_kernel(
    const float* __restrict__ A, const float* __restrict__ B,
    __half* __restrict__ C, int Mdim, int Ndim, int Kdim)
{
    __shared__ float As[8][132];
    __shared__ float Bs[8][132];
    const int tid = threadIdx.x;
    const int m0 = blockIdx.y * 128, n0 = blockIdx.x * 128;
    const int dr = tid >> 5, dc = (tid & 31) * 4;
    const int tx = tid & 15, ty = tid >> 4;
    float acc[8][8];
    #pragma unroll
    for (int i = 0; i < 8; i++)
        #pragma unroll
        for (int j = 0; j < 8; j++) acc[i][j] = 0.f;

    for (int k0 = 0; k0 < Kdim; k0 += 8) {
        float4 av = *(const float4*)(A + (size_t)(k0 + dr) * Mdim + m0 + dc);
        float4 bv = *(const float4*)(B + (size_t)(k0 + dr) * Ndim + n0 + dc);
        __syncthreads();
        *(float4*)&As[dr][dc] = av;
        *(float4*)&Bs[dr][dc] = bv;
        __syncthreads();
        #pragma unroll
        for (int kk = 0; kk < 8; kk++) {
            float a[8], bb[8];
            *(float4*)(a)     = *(const float4*)&As[kk][ty*8];
            *(float4*)(a + 4) = *(const float4*)&As[kk][ty*8 + 4];
            *(float4*)(bb)     = *(const float4*)&Bs[kk][tx*8];
            *(float4*)(bb + 4) = *(const float4*)&Bs[kk][tx*8 + 4];
            #pragma unroll
            for (int i = 0; i < 8; i++)
                #pragma unroll
                for (int j = 0; j < 8; j++)
                    acc[i][j] = fmaf(a[i], bb[j], acc[i][j]);
        }
    }
    #pragma unroll
    for (int i = 0; i < 8; i++) {
        __half* cp = C + (size_t)(m0 + ty*8 + i) * Ndim + n0 + tx*8;
        #pragma unroll
        for (int j = 0; j < 8; j++) cp[j] = __float2half_rn(acc[i][j]);
    }
}

// ============================================================================
// fp16 tensor-core NT GEMM (batched): C[z][M,N] = scale * A[z][M,K] @ B[z][N,K]^T
// Block tile 128x128, BK=32, 8 warps (2m x 4n), warp tile 64x32.
// mma.sync.m16n8k16.f16, ldmatrix.x4 fragment loads.
// Smem: rows of 32 data halves at stride 40 halves (80B) => ldmatrix rows
// r*80 mod 128 cycle all 8 bank-groups -> conflict-free. Double-buffered.
// ============================================================================
__device__ __forceinline__ void ldsm_x4(uint32_t& r0, uint32_t& r1,
                                        uint32_t& r2, uint32_t& r3, uint32_t addr)
{
    asm volatile("ldmatrix.sync.aligned.m8n8.x4.shared.b16 {%0,%1,%2,%3}, [%4];"
                 : "=r"(r0), "=r"(r1), "=r"(r2), "=r"(r3) : "r"(addr));
}

__device__ __forceinline__ void mma_f16(float c[4], const uint32_t a[4],
                                        uint32_t b0, uint32_t b1)
{
    asm volatile(
        "mma.sync.aligned.m16n8k16.row.col.f32.f16.f16.f32 "
        "{%0,%1,%2,%3}, {%4,%5,%6,%7}, {%8,%9}, {%0,%1,%2,%3};"
        : "+f"(c[0]), "+f"(c[1]), "+f"(c[2]), "+f"(c[3])
        : "r"(a[0]), "r"(a[1]), "r"(a[2]), "r"(a[3]), "r"(b0), "r"(b1));
}

template <typename OutT>
__global__ __launch_bounds__(256) void gemm_nt_f16(
    const __half* __restrict__ A, const __half* __restrict__ B,
    OutT* __restrict__ C, int Ndim, int Kdim, float scale,
    size_t aBatch, size_t bBatch, size_t cBatch)
{
    __shared__ __half As[2][128 * 40];
    __shared__ __half Bs[2][128 * 40];

    const int tid  = threadIdx.x;
    const int lane = tid & 31;
    const int warp = tid >> 5;
    const int warp_m = warp & 1;   // 2 warps along m (64 rows each)
    const int warp_n = warp >> 1;  // 4 warps along n (32 cols each)
    const int m0 = blockIdx.y * 128, n0 = blockIdx.x * 128;

    const __half* Az = A + (size_t)blockIdx.z * aBatch;
    const __half* Bz = B + (size_t)blockIdx.z * bBatch;
    OutT*         Cz = C + (size_t)blockIdx.z * cBatch;

    // global loader: thread -> (row, 8-half chunk); rows row and row+64
    const int lrow = tid >> 2;
    const int lcol = (tid & 3) * 8;
    const __half* aPtr = Az + (size_t)(m0 + lrow) * Kdim + lcol;
    const __half* bPtr = Bz + (size_t)(n0 + lrow) * Kdim + lcol;
    const int sIdx = lrow * 40 + lcol;           // smem store index (halves)

    // per-lane ldmatrix offsets (bytes)
    const uint32_t aOff = (uint32_t)(((warp_m * 64 + (lane & 15)) * 40
                                      + (lane >> 4) * 8) * 2);
    const int brow = warp_n * 32 + (lane & 7) + ((lane >> 4) << 3);
    const uint32_t bOff = (uint32_t)((brow * 40 + ((lane >> 3) & 1) * 8) * 2);

    float acc[4][4][4];
    #pragma unroll
    for (int i = 0; i < 4; i++)
        #pragma unroll
        for (int j = 0; j < 4; j++)
            #pragma unroll
            for (int k = 0; k < 4; k++) acc[i][j][k] = 0.f;

    // prologue: stage k0 = 0 into buffer 0
    {
        uint4 a0 = *(const uint4*)(aPtr);
        uint4 a1 = *(const uint4*)(aPtr + (size_t)64 * Kdim);
        uint4 b0 = *(const uint4*)(bPtr);
        uint4 b1 = *(const uint4*)(bPtr + (size_t)64 * Kdim);
        *(uint4*)&As[0][sIdx]           = a0;
        *(uint4*)&As[0][sIdx + 64 * 40] = a1;
        *(uint4*)&Bs[0][sIdx]           = b0;
        *(uint4*)&Bs[0][sIdx + 64 * 40] = b1;
    }
    __syncthreads();

    int cur = 0;
    for (int k0 = 0; k0 < Kdim; k0 += 32) {
        const bool has_next = (k0 + 32) < Kdim;
        uint4 ra0, ra1, rb0, rb1;
        if (has_next) {
            const __half* ap = aPtr + k0 + 32;
            const __half* bp = bPtr + k0 + 32;
            ra0 = *(const uint4*)(ap);
            ra1 = *(const uint4*)(ap + (size_t)64 * Kdim);
            rb0 = *(const uint4*)(bp);
            rb1 = *(const uint4*)(bp + (size_t)64 * Kdim);
        }

        const uint32_t asBase = (uint32_t)__cvta_generic_to_shared(&As[cur][0]);
        const uint32_t bsBase = (uint32_t)__cvta_generic_to_shared(&Bs[cur][0]);
        #pragma unroll
        for (int kk = 0; kk < 32; kk += 16) {
            uint32_t afr[4][4], bfr[2][4];
            #pragma unroll
            for (int wm = 0; wm < 4; wm++)
                ldsm_x4(afr[wm][0], afr[wm][1], afr[wm][2], afr[wm][3],
                        asBase + aOff + wm * (16 * 80) + kk * 2);
            #pragma unroll
            for (int p = 0; p < 2; p++)
                ldsm_x4(bfr[p][0], bfr[p][1], bfr[p][2], bfr[p][3],
                        bsBase + bOff + p * (16 * 80) + kk * 2);
            #pragma unroll
            for (int wm = 0; wm < 4; wm++) {
                mma_f16(acc[wm][0], afr[wm], bfr[0][0], bfr[0][1]);
                mma_f16(acc[wm][1], afr[wm], bfr[0][2], bfr[0][3]);
                mma_f16(acc[wm][2], afr[wm], bfr[1][0], bfr[1][1]);
                mma_f16(acc[wm][3], afr[wm], bfr[1][2], bfr[1][3]);
            }
        }

        if (has_next) {
            const int nxt = cur ^ 1;
            *(uint4*)&As[nxt][sIdx]           = ra0;
            *(uint4*)&As[nxt][sIdx + 64 * 40] = ra1;
            *(uint4*)&Bs[nxt][sIdx]           = rb0;
            *(uint4*)&Bs[nxt][sIdx + 64 * 40] = rb1;
            __syncthreads();
            cur = nxt;
        }
    }

    // epilogue
    #pragma unroll
    for (int wm = 0; wm < 4; wm++) {
        const int r = m0 + warp_m * 64 + wm * 16 + (lane >> 2);
        #pragma unroll
        for (int wn = 0; wn < 4; wn++) {
            const int c = n0 + warp_n * 32 + wn * 8 + 2 * (lane & 3);
            if constexpr (sizeof(OutT) == 4) {
                float2 v0, v1;
                v0.x = acc[wm][wn][0] * scale; v0.y = acc[wm][wn][1] * scale;
                v1.x = acc[wm][wn][2] * scale; v1.y = acc[wm][wn][3] * scale;
                *(float2*)&Cz[(size_t)r * Ndim + c]       = v0;
                *(float2*)&Cz[(size_t)(r + 8) * Ndim + c] = v1;
            } else {
                __half2 h0 = __floats2half2_rn(acc[wm][wn][0] * scale,
                                               acc[wm][wn][1] * scale);
                __half2 h1 = __floats2half2_rn(acc[wm][wn][2] * scale,
                                               acc[wm][wn][3] * scale);
                *(__half2*)&Cz[(size_t)r * Ndim + c]       = h0;
                *(__half2*)&Cz[(size_t)(r + 8) * Ndim + c] = h1;
            }
        }
    }
}

// ============================================================================
// Softmax over each E row + mean over q into w[b,k].
// ============================================================================
__global__ __launch_bounds__(256) void softmax_w_kernel(float* __restrict__ w)
{
    __shared__ float ws[SEQ];
    const int b = blockIdx.y;
    const int qbase = blockIdx.x * 128;
    const int tid = threadIdx.x, lane = tid & 31, warp = tid >> 5;

    for (int i = tid; i < SEQ; i += 256) ws[i] = 0.f;
    __syncthreads();

    float acc[64];
    #pragma unroll
    for (int j = 0; j < 64; j++) acc[j] = 0.f;

    const float* Eb = g_E + (size_t)b * SEQ * SEQ;
    for (int r = 0; r < 16; r++) {
        const int q = qbase + warp * 16 + r;
        const float* row = Eb + (size_t)q * SEQ;
        float m = -1e30f;
        #pragma unroll 8
        for (int j = 0; j < 64; j++) m = fmaxf(m, row[lane + 32 * j]);
        #pragma unroll
        for (int o = 16; o; o >>= 1) m = fmaxf(m, __shfl_xor_sync(~0u, m, o));
        float z = 0.f;
        #pragma unroll 8
        for (int j = 0; j < 64; j++) z += __expf(row[lane + 32 * j] - m);
        #pragma unroll
        for (int o = 16; o; o >>= 1) z += __shfl_xor_sync(~0u, z, o);
        const float inv = 1.0f / z;
        #pragma unroll 8
        for (int j = 0; j < 64; j++)
            acc[j] += __expf(row[lane + 32 * j] - m) * inv;
    }

    #pragma unroll 8
    for (int j = 0; j < 64; j++) atomicAdd(&ws[lane + 32 * j], acc[j]);
    __syncthreads();
    const float invS = 1.0f / (float)SEQ;
    for (int k = tid; k < SEQ; k += 256)
        atomicAdd(&w[b * SEQ + k], ws[k] * invS);
}

// u[b,h] = sum_s w[b,s] * x[b,s,h]
__global__ __launch_bounds__(256) void ctx_u_kernel(
    const float* __restrict__ x, const float* __restrict__ w)
{
    const int b = blockIdx.y;
    const int h = blockIdx.x * 256 + threadIdx.x;
    const int s0 = blockIdx.z * 256;
    const float* xb = x + ((size_t)b * SEQ + s0) * HID + h;
    const float* wb = w + b * SEQ + s0;
    float acc = 0.f;
    #pragma unroll 4
    for (int s = 0; s < 256; s++)
        acc = fmaf(wb[s], xb[(size_t)s * HID], acc);
    atomicAdd(&g_U[b * HID + h], acc);
}

// context[b,o] = sum_h u[b,h] * Wv[o,h]
__global__ __launch_bounds__(256) void ctx_out_kernel(
    const float* __restrict__ Wv, float* __restrict__ ctx)
{
    const int gid = blockIdx.x * 8 + (threadIdx.x >> 5);
    const int lane = threadIdx.x & 31;
    const int b = gid >> 10;
    const int o = gid & 1023;
    const float* ur = g_U + b * HID;
    const float* wr = Wv + (size_t)o * HID;
    float a = 0.f;
    #pragma unroll 8
    for (int h = lane; h < HID; h += 32) a = fmaf(ur[h], wr[h], a);
    #pragma unroll
    for (int off = 16; off; off >>= 1) a += __shfl_xor_sync(~0u, a, off);
    if (lane == 0) ctx[b * HID + o] = a;
}

__global__ void init_kernel(float* __restrict__ w)
{
    const int i = blockIdx.x * 256 + threadIdx.x;
    if (i < BCNT * SEQ) w[i] = 0.f;
    if (i < BCNT * HID) g_U[i] = 0.f;
}

// ============================================================================
extern "C" void kernel_launch(void* const* d_in, const int* in_sizes, int n_in,
                              void* d_out, int out_size)
{
    const float* x  = (const float*)d_in[0];   // (16,2048,1024)
    const float* Wq = (const float*)d_in[1];   // (1024,1024) (out,in)
    const float* Wk = (const float*)d_in[2];
    const float* Wv = (const float*)d_in[3];
    float* out = (float*)d_out;
    float* ctx = out;                  // context      (16,1024)
    float* w   = out + BCNT * HID;     // attn_weights (16,2048)

    __half *pXh, *pMth, *pGh;
    float *pE;
    cudaGetSymbolAddress((void**)&pXh, g_xh);
    cudaGetSymbolAddress((void**)&pMth, g_Mth);
    cudaGetSymbolAddress((void**)&pGh, g_Gh);
    cudaGetSymbolAddress((void**)&pE, g_E);

    init_kernel<<<128, 256>>>(w);

    // x -> fp16 (33.5M elements, 8.4M float4s)
    convert_x_kernel<<<(MTOT * (HID/4)) / 256, 256>>>(
        (const float4*)x, (uint2*)pXh);

    // Mt = Wk^T @ Wq (fp32 accumulate, fp16 out)
    gemm_tn_kernel<<<dim3(8, 8), 256>>>(Wk, Wq, pMth, HID, HID, HID);

    // G = xh @ Mth^T (32768x1024, K=1024) -> fp16
    gemm_nt_f16<__half><<<dim3(8, 256, 1), 256>>>(
        pXh, pMth, pGh, HID, HID, 1.0f, 0, 0, 0);

    // E[b] = Gh[b] @ xh[b]^T / 32 (16 x 2048x2048, K=1024) -> fp32
    gemm_nt_f16<float><<<dim3(16, 16, BCNT), 256>>>(
        pGh, pXh, pE, SEQ, HID, 1.0f / 32.0f,
        (size_t)SEQ * HID, (size_t)SEQ * HID, (size_t)SEQ * SEQ);

    // softmax rows of E, mean over q -> w[b,k]
    softmax_w_kernel<<<dim3(16, BCNT), 256>>>(w);

    // u = w @ x ; context = u @ Wv^T
    ctx_u_kernel<<<dim3(4, BCNT, 8), 256>>>(x, w);
    ctx_out_kernel<<<BCNT * HID / 8, 256>>>(Wv, ctx);
}

// round 6
// speedup vs baseline: 4.5237x; 1.0839x over previous
#include <cuda_runtime.h>
#include <cuda_fp16.h>
#include <stdint.h>

#define BCNT 16
#define SEQ  2048
#define HID  1024
#define MTOT (BCNT*SEQ)   // 32768

// ---- scratch (static device globals: allocation-free per harness rules) ----
__device__ __half g_xh[(size_t)MTOT*HID];            // x in fp16          (64 MB)
__device__ __half g_Mth[HID*HID];                    // (Wk^T Wq) fp16     (2 MB)
__device__ __half g_Gh[(size_t)MTOT*HID];            // x @ M fp16         (64 MB)
__device__ __half g_Eh[(size_t)BCNT*SEQ*SEQ];        // energy fp16        (128 MB)
__device__ float  g_U[BCNT*HID];                     // w @ x              (64 KB)

// ============================================================================
// helpers
// ============================================================================
__device__ __forceinline__ uint32_t smem_u32(const void* p) {
    return (uint32_t)__cvta_generic_to_shared(p);
}
#define CP16(smem, gptr) \
    asm volatile("cp.async.cg.shared.global [%0], [%1], 16;" \
                 :: "r"(smem), "l"(gptr) : "memory")
#define CP_COMMIT() asm volatile("cp.async.commit_group;" ::: "memory")
#define CP_WAIT(n)  asm volatile("cp.async.wait_group %0;" :: "n"(n) : "memory")

__device__ __forceinline__ void ldsm_x4(uint32_t r[4], uint32_t addr)
{
    asm volatile("ldmatrix.sync.aligned.m8n8.x4.shared.b16 {%0,%1,%2,%3}, [%4];"
                 : "=r"(r[0]), "=r"(r[1]), "=r"(r[2]), "=r"(r[3]) : "r"(addr));
}
__device__ __forceinline__ void mma_f16(float c[4], const uint32_t a[4],
                                        uint32_t b0, uint32_t b1)
{
    asm volatile(
        "mma.sync.aligned.m16n8k16.row.col.f32.f16.f16.f32 "
        "{%0,%1,%2,%3}, {%4,%5,%6,%7}, {%8,%9}, {%0,%1,%2,%3};"
        : "+f"(c[0]), "+f"(c[1]), "+f"(c[2]), "+f"(c[3])
        : "r"(a[0]), "r"(a[1]), "r"(a[2]), "r"(a[3]), "r"(b0), "r"(b1));
}

// ============================================================================
// fp16 NT GEMM (batched): C[z][M,N] = scale * A[z][M,K] @ B[z][N,K]^T
// Block tile 128(M) x 256(N), BK=32, 8 warps as 2(m) x 4(n) -> warp tile 64x64.
// 3-stage cp.async pipeline. Smem rows: 32 data halves @ 40-half (80B) pitch
// -> ldmatrix row addresses r*80 mod 128 hit all 8 16B banks (conflict-free).
// Stage = A(128x40x2=10240B) + B(256x40x2=20480B) = 30720B; 3 stages = 92160B.
// ============================================================================
#define STAGE_BYTES 30720
#define NSTAGE 3

template <typename OutT>
__global__ __launch_bounds__(256, 1) void gemm_nt_f16(
    const __half* __restrict__ A, const __half* __restrict__ B,
    OutT* __restrict__ C, int ldc, int Kdim, float scale,
    size_t aBatch, size_t bBatch, size_t cBatch)
{
    extern __shared__ char smem_raw[];
    const uint32_t sbase = smem_u32(smem_raw);

    const int tid  = threadIdx.x;
    const int lane = tid & 31;
    const int warp = tid >> 5;
    const int warp_m = warp & 1;   // 2 warps along m (64 rows each)
    const int warp_n = warp >> 1;  // 4 warps along n (64 cols each)
    const int m0 = blockIdx.y * 128, n0 = blockIdx.x * 256;

    const __half* gA = A + (size_t)blockIdx.z * aBatch + (size_t)m0 * Kdim;
    const __half* gB = B + (size_t)blockIdx.z * bBatch + (size_t)n0 * Kdim;
    OutT*         Cz = C + (size_t)blockIdx.z * cBatch;

    // ldmatrix per-lane byte offsets within a stage
    const uint32_t aOff = (uint32_t)(((warp_m * 64 + (lane & 15)) * 40
                                      + (lane >> 4) * 8) * 2);
    const int brow = warp_n * 64 + (lane & 7) + ((lane >> 4) << 3);
    const uint32_t bOff = (uint32_t)((brow * 40 + ((lane >> 3) & 1) * 8) * 2);

    float acc[4][8][4];
    #pragma unroll
    for (int i = 0; i < 4; i++)
        #pragma unroll
        for (int j = 0; j < 8; j++)
            #pragma unroll
            for (int k = 0; k < 4; k++) acc[i][j][k] = 0.f;

    // ---- async loaders: A 512 chunks (2/thread), B 1024 chunks (4/thread)
#define LOAD_STAGE(s, k0)                                                      \
    do {                                                                       \
        const uint32_t sA = sbase + (s) * STAGE_BYTES;                         \
        const uint32_t sB = sA + 10240;                                        \
        _Pragma("unroll")                                                      \
        for (int i = 0; i < 2; i++) {                                          \
            const int id = tid + i * 256;                                      \
            const int row = id >> 2, cc = id & 3;                              \
            CP16(sA + row * 80 + cc * 16,                                      \
                 gA + (size_t)row * Kdim + (k0) + cc * 8);                     \
        }                                                                      \
        _Pragma("unroll")                                                      \
        for (int i = 0; i < 4; i++) {                                          \
            const int id = tid + i * 256;                                      \
            const int row = id >> 2, cc = id & 3;                              \
            CP16(sB + row * 80 + cc * 16,                                      \
                 gB + (size_t)row * Kdim + (k0) + cc * 8);                     \
        }                                                                      \
        CP_COMMIT();                                                           \
    } while (0)

    const int NIT = Kdim >> 5;   // K / 32
    LOAD_STAGE(0, 0);
    LOAD_STAGE(1, 32);

    for (int c = 0; c < NIT; c++) {
        __syncthreads();                     // WAR: everyone done with stage (c+2)%3
        if (c + 2 < NIT) LOAD_STAGE((c + 2) % NSTAGE, (c + 2) * 32);
        else             CP_COMMIT();        // keep group accounting uniform
        CP_WAIT(2);                          // stage c landed (<=2 groups pending)
        __syncthreads();                     // visibility of stage c to all warps

        const uint32_t ab = sbase + (c % NSTAGE) * STAGE_BYTES;
        const uint32_t bb = ab + 10240;
        #pragma unroll
        for (int kk = 0; kk < 32; kk += 16) {
            uint32_t afr[4][4], bfr[4][4];
            #pragma unroll
            for (int wm = 0; wm < 4; wm++)
                ldsm_x4(afr[wm], ab + aOff + wm * 1280 + kk * 2);
            #pragma unroll
            for (int p = 0; p < 4; p++)
                ldsm_x4(bfr[p], bb + bOff + p * 1280 + kk * 2);
            #pragma unroll
            for (int wm = 0; wm < 4; wm++)
                #pragma unroll
                for (int wn = 0; wn < 8; wn++)
                    mma_f16(acc[wm][wn], afr[wm],
                            bfr[wn >> 1][(wn & 1) * 2],
                            bfr[wn >> 1][(wn & 1) * 2 + 1]);
        }
    }
#undef LOAD_STAGE

    // ---- epilogue ----
    #pragma unroll
    for (int wm = 0; wm < 4; wm++) {
        const int r = m0 + warp_m * 64 + wm * 16 + (lane >> 2);
        #pragma unroll
        for (int wn = 0; wn < 8; wn++) {
            const int cI = n0 + warp_n * 64 + wn * 8 + 2 * (lane & 3);
            if constexpr (sizeof(OutT) == 4) {
                float2 v0, v1;
                v0.x = acc[wm][wn][0] * scale; v0.y = acc[wm][wn][1] * scale;
                v1.x = acc[wm][wn][2] * scale; v1.y = acc[wm][wn][3] * scale;
                *(float2*)&Cz[(size_t)r * ldc + cI]       = v0;
                *(float2*)&Cz[(size_t)(r + 8) * ldc + cI] = v1;
            } else {
                __half2 h0 = __floats2half2_rn(acc[wm][wn][0] * scale,
                                               acc[wm][wn][1] * scale);
                __half2 h1 = __floats2half2_rn(acc[wm][wn][2] * scale,
                                               acc[wm][wn][3] * scale);
                *(__half2*)&Cz[(size_t)r * ldc + cI]       = h0;
                *(__half2*)&Cz[(size_t)(r + 8) * ldc + cI] = h1;
            }
        }
    }
}

// ============================================================================
// x (fp32) -> fp16
// ============================================================================
__global__ __launch_bounds__(256) void convert_x_kernel(
    const float4* __restrict__ in, uint2* __restrict__ outp)
{
    const int i = blockIdx.x * 256 + threadIdx.x;
    float4 v = in[i];
    __half2 h0 = __floats2half2_rn(v.x, v.y);
    __half2 h1 = __floats2half2_rn(v.z, v.w);
    uint2 u;
    u.x = *(uint32_t*)&h0;
    u.y = *(uint32_t*)&h1;
    outp[i] = u;
}

// ============================================================================
// fp32 TN GEMM (small): C[M,N] = A[K,M]^T B[K,N], output fp16
// ============================================================================
__global__ __launch_bounds__(256) void gemm_tn_kernel(
    const float* __restrict__ A, const float* __restrict__ B,
    __half* __restrict__ C, int Mdim, int Ndim, int Kdim)
{
    __shared__ float As[8][132];
    __shared__ float Bs[8][132];
    const int tid = threadIdx.x;
    const int m0 = blockIdx.y * 128, n0 = blockIdx.x * 128;
    const int dr = tid >> 5, dc = (tid & 31) * 4;
    const int tx = tid & 15, ty = tid >> 4;
    float acc[8][8];
    #pragma unroll
    for (int i = 0; i < 8; i++)
        #pragma unroll
        for (int j = 0; j < 8; j++) acc[i][j] = 0.f;

    for (int k0 = 0; k0 < Kdim; k0 += 8) {
        float4 av = *(const float4*)(A + (size_t)(k0 + dr) * Mdim + m0 + dc);
        float4 bv = *(const float4*)(B + (size_t)(k0 + dr) * Ndim + n0 + dc);
        __syncthreads();
        *(float4*)&As[dr][dc] = av;
        *(float4*)&Bs[dr][dc] = bv;
        __syncthreads();
        #pragma unroll
        for (int kk = 0; kk < 8; kk++) {
            float a[8], bb[8];
            *(float4*)(a)     = *(const float4*)&As[kk][ty*8];
            *(float4*)(a + 4) = *(const float4*)&As[kk][ty*8 + 4];
            *(float4*)(bb)     = *(const float4*)&Bs[kk][tx*8];
            *(float4*)(bb + 4) = *(const float4*)&Bs[kk][tx*8 + 4];
            #pragma unroll
            for (int i = 0; i < 8; i++)
                #pragma unroll
                for (int j = 0; j < 8; j++)
                    acc[i][j] = fmaf(a[i], bb[j], acc[i][j]);
        }
    }
    #pragma unroll
    for (int i = 0; i < 8; i++) {
        __half* cp = C + (size_t)(m0 + ty*8 + i) * Ndim + n0 + tx*8;
        #pragma unroll
        for (int j = 0; j < 8; j++) cp[j] = __float2half_rn(acc[i][j]);
    }
}

// ============================================================================
// Softmax over each fp16 E row + mean over q into w[b,k].
// ============================================================================
__global__ __launch_bounds__(256) void softmax_w_kernel(float* __restrict__ w)
{
    __shared__ float ws[SEQ];
    const int b = blockIdx.y;
    const int qbase = blockIdx.x * 128;
    const int tid = threadIdx.x, lane = tid & 31, warp = tid >> 5;

    for (int i = tid; i < SEQ; i += 256) ws[i] = 0.f;
    __syncthreads();

    float acc[64];
    #pragma unroll
    for (int j = 0; j < 64; j++) acc[j] = 0.f;

    const __half* Eb = g_Eh + (size_t)b * SEQ * SEQ;
    for (int r = 0; r < 16; r++) {
        const int q = qbase + warp * 16 + r;
        const uint4* row = (const uint4*)(Eb + (size_t)q * SEQ);
        float f[64];
        #pragma unroll
        for (int j = 0; j < 8; j++) {
            uint4 v = row[j * 32 + lane];
            float2 p0 = __half22float2(*(__half2*)&v.x);
            float2 p1 = __half22float2(*(__half2*)&v.y);
            float2 p2 = __half22float2(*(__half2*)&v.z);
            float2 p3 = __half22float2(*(__half2*)&v.w);
            f[j*8+0] = p0.x; f[j*8+1] = p0.y; f[j*8+2] = p1.x; f[j*8+3] = p1.y;
            f[j*8+4] = p2.x; f[j*8+5] = p2.y; f[j*8+6] = p3.x; f[j*8+7] = p3.y;
        }
        float m = -1e30f;
        #pragma unroll
        for (int j = 0; j < 64; j++) m = fmaxf(m, f[j]);
        #pragma unroll
        for (int o = 16; o; o >>= 1) m = fmaxf(m, __shfl_xor_sync(~0u, m, o));
        float z = 0.f;
        #pragma unroll
        for (int j = 0; j < 64; j++) z += __expf(f[j] - m);
        #pragma unroll
        for (int o = 16; o; o >>= 1) z += __shfl_xor_sync(~0u, z, o);
        const float inv = 1.0f / z;
        #pragma unroll
        for (int j = 0; j < 64; j++)
            acc[j] += __expf(f[j] - m) * inv;
    }

    #pragma unroll
    for (int j = 0; j < 8; j++)
        #pragma unroll
        for (int t = 0; t < 8; t++)
            atomicAdd(&ws[(j * 32 + lane) * 8 + t], acc[j * 8 + t]);
    __syncthreads();
    const float invS = 1.0f / (float)SEQ;
    for (int k = tid; k < SEQ; k += 256)
        atomicAdd(&w[b * SEQ + k], ws[k] * invS);
}

// u[b,h] = sum_s w[b,s] * x[b,s,h]  (fp32 x path, exact)
__global__ __launch_bounds__(256) void ctx_u_kernel(
    const float* __restrict__ x, const float* __restrict__ w)
{
    const int b = blockIdx.y;
    const int h = blockIdx.x * 256 + threadIdx.x;
    const int s0 = blockIdx.z * 256;
    const float* xb = x + ((size_t)b * SEQ + s0) * HID + h;
    const float* wb = w + b * SEQ + s0;
    float acc = 0.f;
    #pragma unroll 4
    for (int s = 0; s < 256; s++)
        acc = fmaf(wb[s], xb[(size_t)s * HID], acc);
    atomicAdd(&g_U[b * HID + h], acc);
}

// context[b,o] = sum_h u[b,h] * Wv[o,h]
__global__ __launch_bounds__(256) void ctx_out_kernel(
    const float* __restrict__ Wv, float* __restrict__ ctx)
{
    const int gid = blockIdx.x * 8 + (threadIdx.x >> 5);
    const int lane = threadIdx.x & 31;
    const int b = gid >> 10;
    const int o = gid & 1023;
    const float* ur = g_U + b * HID;
    const float* wr = Wv + (size_t)o * HID;
    float a = 0.f;
    #pragma unroll 8
    for (int h = lane; h < HID; h += 32) a = fmaf(ur[h], wr[h], a);
    #pragma unroll
    for (int off = 16; off; off >>= 1) a += __shfl_xor_sync(~0u, a, off);
    if (lane == 0) ctx[b * HID + o] = a;
}

__global__ void init_kernel(float* __restrict__ w)
{
    const int i = blockIdx.x * 256 + threadIdx.x;
    if (i < BCNT * SEQ) w[i] = 0.f;
    if (i < BCNT * HID) g_U[i] = 0.f;
}

// ============================================================================
extern "C" void kernel_launch(void* const* d_in, const int* in_sizes, int n_in,
                              void* d_out, int out_size)
{
    const float* x  = (const float*)d_in[0];   // (16,2048,1024)
    const float* Wq = (const float*)d_in[1];   // (1024,1024) (out,in)
    const float* Wk = (const float*)d_in[2];
    const float* Wv = (const float*)d_in[3];
    float* out = (float*)d_out;
    float* ctx = out;                  // context      (16,1024)
    float* w   = out + BCNT * HID;     // attn_weights (16,2048)

    __half *pXh, *pMth, *pGh, *pEh;
    cudaGetSymbolAddress((void**)&pXh, g_xh);
    cudaGetSymbolAddress((void**)&pMth, g_Mth);
    cudaGetSymbolAddress((void**)&pGh, g_Gh);
    cudaGetSymbolAddress((void**)&pEh, g_Eh);

    const int GSMEM = STAGE_BYTES * NSTAGE;   // 92160 B
    cudaFuncSetAttribute(gemm_nt_f16<__half>,
                         cudaFuncAttributeMaxDynamicSharedMemorySize, GSMEM);
    cudaFuncSetAttribute(gemm_nt_f16<float>,
                         cudaFuncAttributeMaxDynamicSharedMemorySize, GSMEM);

    init_kernel<<<128, 256>>>(w);

    // x -> fp16
    convert_x_kernel<<<(MTOT * (HID/4)) / 256, 256>>>(
        (const float4*)x, (uint2*)pXh);

    // Mt = Wk^T @ Wq (fp32 accumulate, fp16 out)
    gemm_tn_kernel<<<dim3(8, 8), 256>>>(Wk, Wq, pMth, HID, HID, HID);

    // G = xh @ Mth^T  (32768x1024, K=1024): grid (n=1024/256, m=32768/128)
    gemm_nt_f16<__half><<<dim3(4, 256, 1), 256, GSMEM>>>(
        pXh, pMth, pGh, HID, HID, 1.0f, 0, 0, 0);

    // E[b] = Gh[b] @ xh[b]^T / 32: grid (n=2048/256, m=2048/128, b=16)
    gemm_nt_f16<__half><<<dim3(8, 16, BCNT), 256, GSMEM>>>(
        pGh, pXh, pEh, SEQ, HID, 1.0f / 32.0f,
        (size_t)SEQ * HID, (size_t)SEQ * HID, (size_t)SEQ * SEQ);

    // softmax rows of E, mean over q -> w[b,k]
    softmax_w_kernel<<<dim3(16, BCNT), 256>>>(w);

    // u = w @ x ; context = u @ Wv^T
    ctx_u_kernel<<<dim3(4, BCNT, 8), 256>>>(x, w);
    ctx_out_kernel<<<BCNT * HID / 8, 256>>>(Wv, ctx);
}

// round 7
// speedup vs baseline: 4.8977x; 1.0827x over previous
#include <cuda_runtime.h>
#include <cuda_fp16.h>
#include <stdint.h>

#define BCNT 16
#define SEQ  2048
#define HID  1024
#define MTOT (BCNT*SEQ)   // 32768

// ---- scratch (static device globals: allocation-free per harness rules) ----
__device__ __half g_xh[(size_t)MTOT*HID];            // x in fp16          (64 MB)
__device__ __half g_Mth[HID*HID];                    // (Wk^T Wq) fp16     (2 MB)
__device__ __half g_Gh[(size_t)MTOT*HID];            // x @ M fp16         (64 MB)
__device__ __half g_Eh[(size_t)BCNT*SEQ*SEQ];        // energy fp16        (128 MB)
__device__ float  g_U[BCNT*HID];                     // w @ x              (64 KB)

// ============================================================================
// helpers
// ============================================================================
__device__ __forceinline__ uint32_t smem_u32(const void* p) {
    return (uint32_t)__cvta_generic_to_shared(p);
}
#define CP16(smem, gptr) \
    asm volatile("cp.async.cg.shared.global [%0], [%1], 16;" \
                 :: "r"(smem), "l"(gptr) : "memory")
#define CP_COMMIT() asm volatile("cp.async.commit_group;" ::: "memory")
#define CP_WAIT(n)  asm volatile("cp.async.wait_group %0;" :: "n"(n) : "memory")

__device__ __forceinline__ void ldsm_x4(uint32_t r[4], uint32_t addr)
{
    asm volatile("ldmatrix.sync.aligned.m8n8.x4.shared.b16 {%0,%1,%2,%3}, [%4];"
                 : "=r"(r[0]), "=r"(r[1]), "=r"(r[2]), "=r"(r[3]) : "r"(addr));
}
__device__ __forceinline__ void mma_f16(float c[4], const uint32_t a[4],
                                        uint32_t b0, uint32_t b1)
{
    asm volatile(
        "mma.sync.aligned.m16n8k16.row.col.f32.f16.f16.f32 "
        "{%0,%1,%2,%3}, {%4,%5,%6,%7}, {%8,%9}, {%0,%1,%2,%3};"
        : "+f"(c[0]), "+f"(c[1]), "+f"(c[2]), "+f"(c[3])
        : "r"(a[0]), "r"(a[1]), "r"(a[2]), "r"(a[3]), "r"(b0), "r"(b1));
}

// ============================================================================
// fp16 NT GEMM (batched): C[z][M,N] = scale * A[z][M,K] @ B[z][N,K]^T
// Block tile 128(M) x 128(N), BK=32, 8 warps as 2(m) x 4(n) -> warp tile 64x32.
// 2 CTAs/SM (launch_bounds minCTAs=2) so co-resident CTAs hide each other's
// barrier + cp.async-wait gaps. 3-stage cp.async pipeline.
// Smem rows: 32 halves @ 40-half (80B) pitch -> ldmatrix conflict-free.
// Stage = (128+128)*80 = 20480B; 3 stages = 61440B/CTA; 2 CTAs = 122880B/SM.
// ============================================================================
#define STAGE_BYTES 20480
#define NSTAGE 3

template <typename OutT>
__global__ __launch_bounds__(256, 2) void gemm_nt_f16(
    const __half* __restrict__ A, const __half* __restrict__ B,
    OutT* __restrict__ C, int ldc, int Kdim, float scale,
    size_t aBatch, size_t bBatch, size_t cBatch)
{
    extern __shared__ char smem_raw[];
    const uint32_t sbase = smem_u32(smem_raw);

    const int tid  = threadIdx.x;
    const int lane = tid & 31;
    const int warp = tid >> 5;
    const int warp_m = warp & 1;   // 2 warps along m (64 rows each)
    const int warp_n = warp >> 1;  // 4 warps along n (32 cols each)
    const int m0 = blockIdx.y * 128, n0 = blockIdx.x * 128;

    const __half* gA = A + (size_t)blockIdx.z * aBatch + (size_t)m0 * Kdim;
    const __half* gB = B + (size_t)blockIdx.z * bBatch + (size_t)n0 * Kdim;
    OutT*         Cz = C + (size_t)blockIdx.z * cBatch;

    // ldmatrix per-lane byte offsets within a stage
    const uint32_t aOff = (uint32_t)(((warp_m * 64 + (lane & 15)) * 40
                                      + (lane >> 4) * 8) * 2);
    const int brow = warp_n * 32 + (lane & 7) + ((lane >> 4) << 3);
    const uint32_t bOff = (uint32_t)((brow * 40 + ((lane >> 3) & 1) * 8) * 2);

    float acc[4][4][4];
    #pragma unroll
    for (int i = 0; i < 4; i++)
        #pragma unroll
        for (int j = 0; j < 4; j++)
            #pragma unroll
            for (int k = 0; k < 4; k++) acc[i][j][k] = 0.f;

    // ---- async loaders: A 512 chunks (2/thread), B 512 chunks (2/thread)
#define LOAD_STAGE(s, k0)                                                      \
    do {                                                                       \
        const uint32_t sA = sbase + (s) * STAGE_BYTES;                         \
        const uint32_t sB = sA + 10240;                                        \
        _Pragma("unroll")                                                      \
        for (int i = 0; i < 2; i++) {                                          \
            const int id = tid + i * 256;                                      \
            const int row = id >> 2, cc = id & 3;                              \
            CP16(sA + row * 80 + cc * 16,                                      \
                 gA + (size_t)row * Kdim + (k0) + cc * 8);                     \
        }                                                                      \
        _Pragma("unroll")                                                      \
        for (int i = 0; i < 2; i++) {                                          \
            const int id = tid + i * 256;                                      \
            const int row = id >> 2, cc = id & 3;                              \
            CP16(sB + row * 80 + cc * 16,                                      \
                 gB + (size_t)row * Kdim + (k0) + cc * 8);                     \
        }                                                                      \
        CP_COMMIT();                                                           \
    } while (0)

    const int NIT = Kdim >> 5;   // K / 32
    LOAD_STAGE(0, 0);
    LOAD_STAGE(1, 32);

    for (int c = 0; c < NIT; c++) {
        __syncthreads();                     // WAR: stage (c+2)%3 free for refill
        if (c + 2 < NIT) LOAD_STAGE((c + 2) % NSTAGE, (c + 2) * 32);
        else             CP_COMMIT();        // keep group accounting uniform
        CP_WAIT(2);                          // stage c landed
        __syncthreads();                     // visibility to all warps

        const uint32_t ab = sbase + (c % NSTAGE) * STAGE_BYTES;
        const uint32_t bb = ab + 10240;
        #pragma unroll
        for (int kk = 0; kk < 32; kk += 16) {
            uint32_t afr[4][4], bfr[2][4];
            #pragma unroll
            for (int wm = 0; wm < 4; wm++)
                ldsm_x4(afr[wm], ab + aOff + wm * 1280 + kk * 2);
            #pragma unroll
            for (int p = 0; p < 2; p++)
                ldsm_x4(bfr[p], bb + bOff + p * 1280 + kk * 2);
            #pragma unroll
            for (int wm = 0; wm < 4; wm++)
                #pragma unroll
                for (int wn = 0; wn < 4; wn++)
                    mma_f16(acc[wm][wn], afr[wm],
                            bfr[wn >> 1][(wn & 1) * 2],
                            bfr[wn >> 1][(wn & 1) * 2 + 1]);
        }
    }
#undef LOAD_STAGE

    // ---- epilogue ----
    #pragma unroll
    for (int wm = 0; wm < 4; wm++) {
        const int r = m0 + warp_m * 64 + wm * 16 + (lane >> 2);
        #pragma unroll
        for (int wn = 0; wn < 4; wn++) {
            const int cI = n0 + warp_n * 32 + wn * 8 + 2 * (lane & 3);
            if constexpr (sizeof(OutT) == 4) {
                float2 v0, v1;
                v0.x = acc[wm][wn][0] * scale; v0.y = acc[wm][wn][1] * scale;
                v1.x = acc[wm][wn][2] * scale; v1.y = acc[wm][wn][3] * scale;
                *(float2*)&Cz[(size_t)r * ldc + cI]       = v0;
                *(float2*)&Cz[(size_t)(r + 8) * ldc + cI] = v1;
            } else {
                __half2 h0 = __floats2half2_rn(acc[wm][wn][0] * scale,
                                               acc[wm][wn][1] * scale);
                __half2 h1 = __floats2half2_rn(acc[wm][wn][2] * scale,
                                               acc[wm][wn][3] * scale);
                *(__half2*)&Cz[(size_t)r * ldc + cI]       = h0;
                *(__half2*)&Cz[(size_t)(r + 8) * ldc + cI] = h1;
            }
        }
    }
}

// ============================================================================
// x (fp32) -> fp16
// ============================================================================
__global__ __launch_bounds__(256) void convert_x_kernel(
    const float4* __restrict__ in, uint2* __restrict__ outp)
{
    const int i = blockIdx.x * 256 + threadIdx.x;
    float4 v = in[i];
    __half2 h0 = __floats2half2_rn(v.x, v.y);
    __half2 h1 = __floats2half2_rn(v.z, v.w);
    uint2 u;
    u.x = *(uint32_t*)&h0;
    u.y = *(uint32_t*)&h1;
    outp[i] = u;
}

// ============================================================================
// fp32 TN GEMM (small): C[M,N] = A[K,M]^T B[K,N], output fp16
// ============================================================================
__global__ __launch_bounds__(256) void gemm_tn_kernel(
    const float* __restrict__ A, const float* __restrict__ B,
    __half* __restrict__ C, int Mdim, int Ndim, int Kdim)
{
    __shared__ float As[8][132];
    __shared__ float Bs[8][132];
    const int tid = threadIdx.x;
    const int m0 = blockIdx.y * 128, n0 = blockIdx.x * 128;
    const int dr = tid >> 5, dc = (tid & 31) * 4;
    const int tx = tid & 15, ty = tid >> 4;
    float acc[8][8];
    #pragma unroll
    for (int i = 0; i < 8; i++)
        #pragma unroll
        for (int j = 0; j < 8; j++) acc[i][j] = 0.f;

    for (int k0 = 0; k0 < Kdim; k0 += 8) {
        float4 av = *(const float4*)(A + (size_t)(k0 + dr) * Mdim + m0 + dc);
        float4 bv = *(const float4*)(B + (size_t)(k0 + dr) * Ndim + n0 + dc);
        __syncthreads();
        *(float4*)&As[dr][dc] = av;
        *(float4*)&Bs[dr][dc] = bv;
        __syncthreads();
        #pragma unroll
        for (int kk = 0; kk < 8; kk++) {
            float a[8], bb[8];
            *(float4*)(a)     = *(const float4*)&As[kk][ty*8];
            *(float4*)(a + 4) = *(const float4*)&As[kk][ty*8 + 4];
            *(float4*)(bb)     = *(const float4*)&Bs[kk][tx*8];
            *(float4*)(bb + 4) = *(const float4*)&Bs[kk][tx*8 + 4];
            #pragma unroll
            for (int i = 0; i < 8; i++)
                #pragma unroll
                for (int j = 0; j < 8; j++)
                    acc[i][j] = fmaf(a[i], bb[j], acc[i][j]);
        }
    }
    #pragma unroll
    for (int i = 0; i < 8; i++) {
        __half* cp = C + (size_t)(m0 + ty*8 + i) * Ndim + n0 + tx*8;
        #pragma unroll
        for (int j = 0; j < 8; j++) cp[j] = __float2half_rn(acc[i][j]);
    }
}

// ============================================================================
// Softmax over each fp16 E row + mean over q into w[b,k].
// ============================================================================
__global__ __launch_bounds__(256) void softmax_w_kernel(float* __restrict__ w)
{
    __shared__ float ws[SEQ];
    const int b = blockIdx.y;
    const int qbase = blockIdx.x * 128;
    const int tid = threadIdx.x, lane = tid & 31, warp = tid >> 5;

    for (int i = tid; i < SEQ; i += 256) ws[i] = 0.f;
    __syncthreads();

    float acc[64];
    #pragma unroll
    for (int j = 0; j < 64; j++) acc[j] = 0.f;

    const __half* Eb = g_Eh + (size_t)b * SEQ * SEQ;
    for (int r = 0; r < 16; r++) {
        const int q = qbase + warp * 16 + r;
        const uint4* row = (const uint4*)(Eb + (size_t)q * SEQ);
        float f[64];
        #pragma unroll
        for (int j = 0; j < 8; j++) {
            uint4 v = row[j * 32 + lane];
            float2 p0 = __half22float2(*(__half2*)&v.x);
            float2 p1 = __half22float2(*(__half2*)&v.y);
            float2 p2 = __half22float2(*(__half2*)&v.z);
            float2 p3 = __half22float2(*(__half2*)&v.w);
            f[j*8+0] = p0.x; f[j*8+1] = p0.y; f[j*8+2] = p1.x; f[j*8+3] = p1.y;
            f[j*8+4] = p2.x; f[j*8+5] = p2.y; f[j*8+6] = p3.x; f[j*8+7] = p3.y;
        }
        float m = -1e30f;
        #pragma unroll
        for (int j = 0; j < 64; j++) m = fmaxf(m, f[j]);
        #pragma unroll
        for (int o = 16; o; o >>= 1) m = fmaxf(m, __shfl_xor_sync(~0u, m, o));
        float z = 0.f;
        #pragma unroll
        for (int j = 0; j < 64; j++) z += __expf(f[j] - m);
        #pragma unroll
        for (int o = 16; o; o >>= 1) z += __shfl_xor_sync(~0u, z, o);
        const float inv = 1.0f / z;
        #pragma unroll
        for (int j = 0; j < 64; j++)
            acc[j] += __expf(f[j] - m) * inv;
    }

    #pragma unroll
    for (int j = 0; j < 8; j++)
        #pragma unroll
        for (int t = 0; t < 8; t++)
            atomicAdd(&ws[(j * 32 + lane) * 8 + t], acc[j * 8 + t]);
    __syncthreads();
    const float invS = 1.0f / (float)SEQ;
    for (int k = tid; k < SEQ; k += 256)
        atomicAdd(&w[b * SEQ + k], ws[k] * invS);
}

// u[b,h] = sum_s w[b,s] * x[b,s,h]  (fp32 x path, exact)
__global__ __launch_bounds__(256) void ctx_u_kernel(
    const float* __restrict__ x, const float* __restrict__ w)
{
    const int b = blockIdx.y;
    const int h = blockIdx.x * 256 + threadIdx.x;
    const int s0 = blockIdx.z * 256;
    const float* xb = x + ((size_t)b * SEQ + s0) * HID + h;
    const float* wb = w + b * SEQ + s0;
    float acc = 0.f;
    #pragma unroll 4
    for (int s = 0; s < 256; s++)
        acc = fmaf(wb[s], xb[(size_t)s * HID], acc);
    atomicAdd(&g_U[b * HID + h], acc);
}

// context[b,o] = sum_h u[b,h] * Wv[o,h]
__global__ __launch_bounds__(256) void ctx_out_kernel(
    const float* __restrict__ Wv, float* __restrict__ ctx)
{
    const int gid = blockIdx.x * 8 + (threadIdx.x >> 5);
    const int lane = threadIdx.x & 31;
    const int b = gid >> 10;
    const int o = gid & 1023;
    const float* ur = g_U + b * HID;
    const float* wr = Wv + (size_t)o * HID;
    float a = 0.f;
    #pragma unroll 8
    for (int h = lane; h < HID; h += 32) a = fmaf(ur[h], wr[h], a);
    #pragma unroll
    for (int off = 16; off; off >>= 1) a += __shfl_xor_sync(~0u, a, off);
    if (lane == 0) ctx[b * HID + o] = a;
}

__global__ void init_kernel(float* __restrict__ w)
{
    const int i = blockIdx.x * 256 + threadIdx.x;
    if (i < BCNT * SEQ) w[i] = 0.f;
    if (i < BCNT * HID) g_U[i] = 0.f;
}

// ============================================================================
extern "C" void kernel_launch(void* const* d_in, const int* in_sizes, int n_in,
                              void* d_out, int out_size)
{
    const float* x  = (const float*)d_in[0];   // (16,2048,1024)
    const float* Wq = (const float*)d_in[1];   // (1024,1024) (out,in)
    const float* Wk = (const float*)d_in[2];
    const float* Wv = (const float*)d_in[3];
    float* out = (float*)d_out;
    float* ctx = out;                  // context      (16,1024)
    float* w   = out + BCNT * HID;     // attn_weights (16,2048)

    __half *pXh, *pMth, *pGh, *pEh;
    cudaGetSymbolAddress((void**)&pXh, g_xh);
    cudaGetSymbolAddress((void**)&pMth, g_Mth);
    cudaGetSymbolAddress((void**)&pGh, g_Gh);
    cudaGetSymbolAddress((void**)&pEh, g_Eh);

    const int GSMEM = STAGE_BYTES * NSTAGE;   // 61440 B
    cudaFuncSetAttribute(gemm_nt_f16<__half>,
                         cudaFuncAttributeMaxDynamicSharedMemorySize, GSMEM);
    cudaFuncSetAttribute(gemm_nt_f16<float>,
                         cudaFuncAttributeMaxDynamicSharedMemorySize, GSMEM);

    init_kernel<<<128, 256>>>(w);

    // x -> fp16
    convert_x_kernel<<<(MTOT * (HID/4)) / 256, 256>>>(
        (const float4*)x, (uint2*)pXh);

    // Mt = Wk^T @ Wq (fp32 accumulate, fp16 out)
    gemm_tn_kernel<<<dim3(8, 8), 256>>>(Wk, Wq, pMth, HID, HID, HID);

    // G = xh @ Mth^T  (32768x1024, K=1024): grid (n=1024/128, m=32768/128)
    gemm_nt_f16<__half><<<dim3(8, 256, 1), 256, GSMEM>>>(
        pXh, pMth, pGh, HID, HID, 1.0f, 0, 0, 0);

    // E[b] = Gh[b] @ xh[b]^T / 32: grid (n=2048/128, m=2048/128, b=16)
    gemm_nt_f16<__half><<<dim3(16, 16, BCNT), 256, GSMEM>>>(
        pGh, pXh, pEh, SEQ, HID, 1.0f / 32.0f,
        (size_t)SEQ * HID, (size_t)SEQ * HID, (size_t)SEQ * SEQ);

    // softmax rows of E, mean over q -> w[b,k]
    softmax_w_kernel<<<dim3(16, BCNT), 256>>>(w);

    // u = w @ x ; context = u @ Wv^T
    ctx_u_kernel<<<dim3(4, BCNT, 8), 256>>>(x, w);
    ctx_out_kernel<<<BCNT * HID / 8, 256>>>(Wv, ctx);
}

// round 8
// speedup vs baseline: 4.9860x; 1.0180x over previous
#include <cuda_runtime.h>
#include <cuda_fp16.h>
#include <stdint.h>

#define BCNT 16
#define SEQ  2048
#define HID  1024
#define MTOT (BCNT*SEQ)   // 32768

// ---- scratch (static device globals: allocation-free per harness rules) ----
__device__ __half g_xh[(size_t)MTOT*HID];            // x in fp16          (64 MB)
__device__ __half g_Mth[HID*HID];                    // (Wk^T Wq) fp16     (2 MB)
__device__ __half g_Gh[(size_t)MTOT*HID];            // x @ M fp16         (64 MB)
__device__ __half g_Eh[(size_t)BCNT*SEQ*SEQ];        // energy fp16        (128 MB)
__device__ float  g_U[BCNT*HID];                     // w @ x              (64 KB)

// ============================================================================
// helpers
// ============================================================================
__device__ __forceinline__ uint32_t smem_u32(const void* p) {
    return (uint32_t)__cvta_generic_to_shared(p);
}
#define CP16(smem, gptr) \
    asm volatile("cp.async.cg.shared.global [%0], [%1], 16;" \
                 :: "r"(smem), "l"(gptr) : "memory")
#define CP_COMMIT() asm volatile("cp.async.commit_group;" ::: "memory")
#define CP_WAIT(n)  asm volatile("cp.async.wait_group %0;" :: "n"(n) : "memory")

__device__ __forceinline__ void ldsm_x4(uint32_t r[4], uint32_t addr)
{
    asm volatile("ldmatrix.sync.aligned.m8n8.x4.shared.b16 {%0,%1,%2,%3}, [%4];"
                 : "=r"(r[0]), "=r"(r[1]), "=r"(r[2]), "=r"(r[3]) : "r"(addr));
}
__device__ __forceinline__ void mma_f16(float c[4], const uint32_t a[4],
                                        uint32_t b0, uint32_t b1)
{
    asm volatile(
        "mma.sync.aligned.m16n8k16.row.col.f32.f16.f16.f32 "
        "{%0,%1,%2,%3}, {%4,%5,%6,%7}, {%8,%9}, {%0,%1,%2,%3};"
        : "+f"(c[0]), "+f"(c[1]), "+f"(c[2]), "+f"(c[3])
        : "r"(a[0]), "r"(a[1]), "r"(a[2]), "r"(a[3]), "r"(b0), "r"(b1));
}

// ============================================================================
// fp16 NT GEMM (batched): C[z][M,N] = scale * A[z][M,K] @ B[z][N,K]^T
// Block tile 128(M) x 128(N), BK=32, 8 warps as 2(m) x 4(n) -> warp tile 64x32.
// 2 CTAs/SM. 4-stage cp.async pipeline, ONE __syncthreads per iteration:
//   wait(2) -> sync -> load stage (c+3) -> compute stage c
// WAR safety: stage (c+3)%4 was last computed at iteration c-1... no: at c-2;
// every warp passed this iteration's sync only after finishing compute(c-1),
// hence also compute(c-2) -> overwrite is safe.
// Smem rows: 32 halves @ 40-half (80B) pitch -> ldmatrix conflict-free.
// Stage = (128+128)*80 = 20480B; 4 stages = 81920B/CTA; 2 CTAs = 163840B/SM.
// ============================================================================
#define STAGE_BYTES 20480
#define NSTAGE 4

template <typename OutT>
__global__ __launch_bounds__(256, 2) void gemm_nt_f16(
    const __half* __restrict__ A, const __half* __restrict__ B,
    OutT* __restrict__ C, int ldc, int Kdim, float scale,
    size_t aBatch, size_t bBatch, size_t cBatch)
{
    extern __shared__ char smem_raw[];
    const uint32_t sbase = smem_u32(smem_raw);

    const int tid  = threadIdx.x;
    const int lane = tid & 31;
    const int warp = tid >> 5;
    const int warp_m = warp & 1;   // 2 warps along m (64 rows each)
    const int warp_n = warp >> 1;  // 4 warps along n (32 cols each)
    const int m0 = blockIdx.y * 128, n0 = blockIdx.x * 128;

    const __half* gA = A + (size_t)blockIdx.z * aBatch + (size_t)m0 * Kdim;
    const __half* gB = B + (size_t)blockIdx.z * bBatch + (size_t)n0 * Kdim;
    OutT*         Cz = C + (size_t)blockIdx.z * cBatch;

    // ldmatrix per-lane byte offsets within a stage
    const uint32_t aOff = (uint32_t)(((warp_m * 64 + (lane & 15)) * 40
                                      + (lane >> 4) * 8) * 2);
    const int brow = warp_n * 32 + (lane & 7) + ((lane >> 4) << 3);
    const uint32_t bOff = (uint32_t)((brow * 40 + ((lane >> 3) & 1) * 8) * 2);

    float acc[4][4][4];
    #pragma unroll
    for (int i = 0; i < 4; i++)
        #pragma unroll
        for (int j = 0; j < 4; j++)
            #pragma unroll
            for (int k = 0; k < 4; k++) acc[i][j][k] = 0.f;

    // ---- async loaders: A 2 chunks/thread, B 2 chunks/thread (16B each)
#define LOAD_STAGE(s, k0)                                                      \
    do {                                                                       \
        const uint32_t sA = sbase + (s) * STAGE_BYTES;                         \
        const uint32_t sB = sA + 10240;                                        \
        _Pragma("unroll")                                                      \
        for (int i = 0; i < 2; i++) {                                          \
            const int id = tid + i * 256;                                      \
            const int row = id >> 2, cc = id & 3;                              \
            CP16(sA + row * 80 + cc * 16,                                      \
                 gA + (size_t)row * Kdim + (k0) + cc * 8);                     \
        }                                                                      \
        _Pragma("unroll")                                                      \
        for (int i = 0; i < 2; i++) {                                          \
            const int id = tid + i * 256;                                      \
            const int row = id >> 2, cc = id & 3;                              \
            CP16(sB + row * 80 + cc * 16,                                      \
                 gB + (size_t)row * Kdim + (k0) + cc * 8);                     \
        }                                                                      \
        CP_COMMIT();                                                           \
    } while (0)

    const int NIT = Kdim >> 5;   // K / 32
    LOAD_STAGE(0, 0);
    LOAD_STAGE(1, 32);
    LOAD_STAGE(2, 64);

    for (int c = 0; c < NIT; c++) {
        CP_WAIT(2);                          // stage c landed (3 groups out)
        __syncthreads();                     // visibility + WAR protection
        if (c + 3 < NIT) LOAD_STAGE((c + 3) & (NSTAGE - 1), (c + 3) * 32);
        else             CP_COMMIT();        // keep group accounting uniform

        const uint32_t ab = sbase + (c & (NSTAGE - 1)) * STAGE_BYTES;
        const uint32_t bb = ab + 10240;
        #pragma unroll
        for (int kk = 0; kk < 32; kk += 16) {
            uint32_t afr[4][4], bfr[2][4];
            #pragma unroll
            for (int wm = 0; wm < 4; wm++)
                ldsm_x4(afr[wm], ab + aOff + wm * 1280 + kk * 2);
            #pragma unroll
            for (int p = 0; p < 2; p++)
                ldsm_x4(bfr[p], bb + bOff + p * 1280 + kk * 2);
            #pragma unroll
            for (int wm = 0; wm < 4; wm++)
                #pragma unroll
                for (int wn = 0; wn < 4; wn++)
                    mma_f16(acc[wm][wn], afr[wm],
                            bfr[wn >> 1][(wn & 1) * 2],
                            bfr[wn >> 1][(wn & 1) * 2 + 1]);
        }
    }
#undef LOAD_STAGE

    // ---- epilogue ----
    #pragma unroll
    for (int wm = 0; wm < 4; wm++) {
        const int r = m0 + warp_m * 64 + wm * 16 + (lane >> 2);
        #pragma unroll
        for (int wn = 0; wn < 4; wn++) {
            const int cI = n0 + warp_n * 32 + wn * 8 + 2 * (lane & 3);
            if constexpr (sizeof(OutT) == 4) {
                float2 v0, v1;
                v0.x = acc[wm][wn][0] * scale; v0.y = acc[wm][wn][1] * scale;
                v1.x = acc[wm][wn][2] * scale; v1.y = acc[wm][wn][3] * scale;
                *(float2*)&Cz[(size_t)r * ldc + cI]       = v0;
                *(float2*)&Cz[(size_t)(r + 8) * ldc + cI] = v1;
            } else {
                __half2 h0 = __floats2half2_rn(acc[wm][wn][0] * scale,
                                               acc[wm][wn][1] * scale);
                __half2 h1 = __floats2half2_rn(acc[wm][wn][2] * scale,
                                               acc[wm][wn][3] * scale);
                *(__half2*)&Cz[(size_t)r * ldc + cI]       = h0;
                *(__half2*)&Cz[(size_t)(r + 8) * ldc + cI] = h1;
            }
        }
    }
}

// ============================================================================
// x (fp32) -> fp16
// ============================================================================
__global__ __launch_bounds__(256) void convert_x_kernel(
    const float4* __restrict__ in, uint2* __restrict__ outp)
{
    const int i = blockIdx.x * 256 + threadIdx.x;
    float4 v = in[i];
    __half2 h0 = __floats2half2_rn(v.x, v.y);
    __half2 h1 = __floats2half2_rn(v.z, v.w);
    uint2 u;
    u.x = *(uint32_t*)&h0;
    u.y = *(uint32_t*)&h1;
    outp[i] = u;
}

// ============================================================================
// fp32 TN GEMM (small): C[M,N] = A[K,M]^T B[K,N], output fp16
// ============================================================================
__global__ __launch_bounds__(256) void gemm_tn_kernel(
    const float* __restrict__ A, const float* __restrict__ B,
    __half* __restrict__ C, int Mdim, int Ndim, int Kdim)
{
    __shared__ float As[8][132];
    __shared__ float Bs[8][132];
    const int tid = threadIdx.x;
    const int m0 = blockIdx.y * 128, n0 = blockIdx.x * 128;
    const int dr = tid >> 5, dc = (tid & 31) * 4;
    const int tx = tid & 15, ty = tid >> 4;
    float acc[8][8];
    #pragma unroll
    for (int i = 0; i < 8; i++)
        #pragma unroll
        for (int j = 0; j < 8; j++) acc[i][j] = 0.f;

    for (int k0 = 0; k0 < Kdim; k0 += 8) {
        float4 av = *(const float4*)(A + (size_t)(k0 + dr) * Mdim + m0 + dc);
        float4 bv = *(const float4*)(B + (size_t)(k0 + dr) * Ndim + n0 + dc);
        __syncthreads();
        *(float4*)&As[dr][dc] = av;
        *(float4*)&Bs[dr][dc] = bv;
        __syncthreads();
        #pragma unroll
        for (int kk = 0; kk < 8; kk++) {
            float a[8], bb[8];
            *(float4*)(a)     = *(const float4*)&As[kk][ty*8];
            *(float4*)(a + 4) = *(const float4*)&As[kk][ty*8 + 4];
            *(float4*)(bb)     = *(const float4*)&Bs[kk][tx*8];
            *(float4*)(bb + 4) = *(const float4*)&Bs[kk][tx*8 + 4];
            #pragma unroll
            for (int i = 0; i < 8; i++)
                #pragma unroll
                for (int j = 0; j < 8; j++)
                    acc[i][j] = fmaf(a[i], bb[j], acc[i][j]);
        }
    }
    #pragma unroll
    for (int i = 0; i < 8; i++) {
        __half* cp = C + (size_t)(m0 + ty*8 + i) * Ndim + n0 + tx*8;
        #pragma unroll
        for (int j = 0; j < 8; j++) cp[j] = __float2half_rn(acc[i][j]);
    }
}

// ============================================================================
// Softmax over each fp16 E row + mean over q into w[b,k].  exp computed ONCE.
// ============================================================================
__global__ __launch_bounds__(256) void softmax_w_kernel(float* __restrict__ w)
{
    __shared__ float ws[SEQ];
    const int b = blockIdx.y;
    const int qbase = blockIdx.x * 128;
    const int tid = threadIdx.x, lane = tid & 31, warp = tid >> 5;

    for (int i = tid; i < SEQ; i += 256) ws[i] = 0.f;
    __syncthreads();

    float acc[64];
    #pragma unroll
    for (int j = 0; j < 64; j++) acc[j] = 0.f;

    const __half* Eb = g_Eh + (size_t)b * SEQ * SEQ;
    for (int r = 0; r < 16; r++) {
        const int q = qbase + warp * 16 + r;
        const uint4* row = (const uint4*)(Eb + (size_t)q * SEQ);
        float f[64];
        #pragma unroll
        for (int j = 0; j < 8; j++) {
            uint4 v = row[j * 32 + lane];
            float2 p0 = __half22float2(*(__half2*)&v.x);
            float2 p1 = __half22float2(*(__half2*)&v.y);
            float2 p2 = __half22float2(*(__half2*)&v.z);
            float2 p3 = __half22float2(*(__half2*)&v.w);
            f[j*8+0] = p0.x; f[j*8+1] = p0.y; f[j*8+2] = p1.x; f[j*8+3] = p1.y;
            f[j*8+4] = p2.x; f[j*8+5] = p2.y; f[j*8+6] = p3.x; f[j*8+7] = p3.y;
        }
        float m = -1e30f;
        #pragma unroll
        for (int j = 0; j < 64; j++) m = fmaxf(m, f[j]);
        #pragma unroll
        for (int o = 16; o; o >>= 1) m = fmaxf(m, __shfl_xor_sync(~0u, m, o));
        float z = 0.f;
        #pragma unroll
        for (int j = 0; j < 64; j++) { f[j] = __expf(f[j] - m); z += f[j]; }
        #pragma unroll
        for (int o = 16; o; o >>= 1) z += __shfl_xor_sync(~0u, z, o);
        const float inv = 1.0f / z;
        #pragma unroll
        for (int j = 0; j < 64; j++)
            acc[j] = fmaf(f[j], inv, acc[j]);
    }

    #pragma unroll
    for (int j = 0; j < 8; j++)
        #pragma unroll
        for (int t = 0; t < 8; t++)
            atomicAdd(&ws[(j * 32 + lane) * 8 + t], acc[j * 8 + t]);
    __syncthreads();
    const float invS = 1.0f / (float)SEQ;
    for (int k = tid; k < SEQ; k += 256)
        atomicAdd(&w[b * SEQ + k], ws[k] * invS);
}

// u[b,h] = sum_s w[b,s] * x[b,s,h]  (fp32 x path, exact)
__global__ __launch_bounds__(256) void ctx_u_kernel(
    const float* __restrict__ x, const float* __restrict__ w)
{
    const int b = blockIdx.y;
    const int h = blockIdx.x * 256 + threadIdx.x;
    const int s0 = blockIdx.z * 256;
    const float* xb = x + ((size_t)b * SEQ + s0) * HID + h;
    const float* wb = w + b * SEQ + s0;
    float acc = 0.f;
    #pragma unroll 4
    for (int s = 0; s < 256; s++)
        acc = fmaf(wb[s], xb[(size_t)s * HID], acc);
    atomicAdd(&g_U[b * HID + h], acc);
}

// context[b,o] = sum_h u[b,h] * Wv[o,h]
__global__ __launch_bounds__(256) void ctx_out_kernel(
    const float* __restrict__ Wv, float* __restrict__ ctx)
{
    const int gid = blockIdx.x * 8 + (threadIdx.x >> 5);
    const int lane = threadIdx.x & 31;
    const int b = gid >> 10;
    const int o = gid & 1023;
    const float* ur = g_U + b * HID;
    const float* wr = Wv + (size_t)o * HID;
    float a = 0.f;
    #pragma unroll 8
    for (int h = lane; h < HID; h += 32) a = fmaf(ur[h], wr[h], a);
    #pragma unroll
    for (int off = 16; off; off >>= 1) a += __shfl_xor_sync(~0u, a, off);
    if (lane == 0) ctx[b * HID + o] = a;
}

__global__ void init_kernel(float* __restrict__ w)
{
    const int i = blockIdx.x * 256 + threadIdx.x;
    if (i < BCNT * SEQ) w[i] = 0.f;
    if (i < BCNT * HID) g_U[i] = 0.f;
}

// ============================================================================
extern "C" void kernel_launch(void* const* d_in, const int* in_sizes, int n_in,
                              void* d_out, int out_size)
{
    const float* x  = (const float*)d_in[0];   // (16,2048,1024)
    const float* Wq = (const float*)d_in[1];   // (1024,1024) (out,in)
    const float* Wk = (const float*)d_in[2];
    const float* Wv = (const float*)d_in[3];
    float* out = (float*)d_out;
    float* ctx = out;                  // context      (16,1024)
    float* w   = out + BCNT * HID;     // attn_weights (16,2048)

    __half *pXh, *pMth, *pGh, *pEh;
    cudaGetSymbolAddress((void**)&pXh, g_xh);
    cudaGetSymbolAddress((void**)&pMth, g_Mth);
    cudaGetSymbolAddress((void**)&pGh, g_Gh);
    cudaGetSymbolAddress((void**)&pEh, g_Eh);

    const int GSMEM = STAGE_BYTES * NSTAGE;   // 81920 B
    cudaFuncSetAttribute(gemm_nt_f16<__half>,
                         cudaFuncAttributeMaxDynamicSharedMemorySize, GSMEM);
    cudaFuncSetAttribute(gemm_nt_f16<float>,
                         cudaFuncAttributeMaxDynamicSharedMemorySize, GSMEM);

    init_kernel<<<128, 256>>>(w);

    // x -> fp16
    convert_x_kernel<<<(MTOT * (HID/4)) / 256, 256>>>(
        (const float4*)x, (uint2*)pXh);

    // Mt = Wk^T @ Wq (fp32 accumulate, fp16 out)
    gemm_tn_kernel<<<dim3(8, 8), 256>>>(Wk, Wq, pMth, HID, HID, HID);

    // G = xh @ Mth^T  (32768x1024, K=1024): grid (n=1024/128, m=32768/128)
    gemm_nt_f16<__half><<<dim3(8, 256, 1), 256, GSMEM>>>(
        pXh, pMth, pGh, HID, HID, 1.0f, 0, 0, 0);

    // E[b] = Gh[b] @ xh[b]^T / 32: grid (n=2048/128, m=2048/128, b=16)
    gemm_nt_f16<__half><<<dim3(16, 16, BCNT), 256, GSMEM>>>(
        pGh, pXh, pEh, SEQ, HID, 1.0f / 32.0f,
        (size_t)SEQ * HID, (size_t)SEQ * HID, (size_t)SEQ * SEQ);

    // softmax rows of E, mean over q -> w[b,k]
    softmax_w_kernel<<<dim3(16, BCNT), 256>>>(w);

    // u = w @ x ; context = u @ Wv^T
    ctx_u_kernel<<<dim3(4, BCNT, 8), 256>>>(x, w);
    ctx_out_kernel<<<BCNT * HID / 8, 256>>>(Wv, ctx);
}